// round 9
// baseline (speedup 1.0000x reference)
#include <cuda_runtime.h>
#include <cuda_fp16.h>
#include <math.h>
#include <stdint.h>

// Problem constants
#define BB 4
#define HH 16
#define SS 2048
#define DD 1024
#define HD 64
#define MROWS (BB * SS)   // 8192

// ---------------------------------------------------------------------------
// Scratch (no allocations allowed -> __device__ globals)
// ---------------------------------------------------------------------------
__device__ __half g_Qh[BB * HH * SS * HD];
__device__ __half g_Kh[BB * HH * SS * HD];
__device__ __half g_Vt[BB * HH * HD * SS];   // [b,h,d,s] transposed
__device__ __half g_ctx[BB * SS * DD];
__device__ __half g_Xh[MROWS * DD];
__device__ __half g_Wh[4 * DD * DD];         // Wq|Wk|Wv|Wo (rows n, k-major)
__device__ float  g_bias[3 * DD];            // bq|bk|bv

// ---------------------------------------------------------------------------
// helpers
// ---------------------------------------------------------------------------
__device__ __forceinline__ uint32_t smem_u32(const void* p) {
    uint32_t a;
    asm("{ .reg .u64 t; cvta.to.shared.u64 t, %1; cvt.u32.u64 %0, t; }"
        : "=r"(a) : "l"(p));
    return a;
}

// mma.sync m16n8k16 fp16 in, fp32 accumulate (in place on d)
__device__ __forceinline__ void mma_f16(float d[4], const uint32_t a[4],
                                        const uint32_t b[2]) {
    asm volatile(
        "mma.sync.aligned.m16n8k16.row.col.f32.f16.f16.f32 "
        "{%0,%1,%2,%3}, {%4,%5,%6,%7}, {%8,%9}, {%0,%1,%2,%3};"
        : "+f"(d[0]), "+f"(d[1]), "+f"(d[2]), "+f"(d[3])
        : "r"(a[0]), "r"(a[1]), "r"(a[2]), "r"(a[3]), "r"(b[0]), "r"(b[1]));
}

// ---------------------------------------------------------------------------
// fp32 -> fp16 convert ; bias concat
// ---------------------------------------------------------------------------
__global__ void cvt_kernel(const float* __restrict__ in,
                           __half* __restrict__ out, int n4)
{
    int i = blockIdx.x * blockDim.x + threadIdx.x;
    if (i < n4) {
        float4 v = ((const float4*)in)[i];
        ((__half2*)out)[2 * i]     = __floats2half2_rn(v.x, v.y);
        ((__half2*)out)[2 * i + 1] = __floats2half2_rn(v.z, v.w);
    }
}

__global__ void pack_bias_kernel(const float* __restrict__ bq,
                                 const float* __restrict__ bk,
                                 const float* __restrict__ bv,
                                 float* __restrict__ out)
{
    int i = blockIdx.x * blockDim.x + threadIdx.x;   // < 3072
    float v;
    if (i < 1024) v = bq[i];
    else if (i < 2048) v = bk[i - 1024];
    else v = bv[i - 2048];
    out[i] = v;
}

// ===========================================================================
// Shared GEMM machinery: CTA tile 128x128, BK=32 halves, 8 warps (4m x 2n),
// warp tile 32x64. 4-stage cp.async ring (82KB smem, 2 CTAs/SM).
// ===========================================================================
#define GBK 32
#define GPADH 40
#define GSTAGE_BYTES (2 * 128 * GPADH * 2)   // 20480
#define GNSTAGE 4
#define GEMM_SMEM (GNSTAGE * GSTAGE_BYTES)   // 81920

__device__ __forceinline__ void gemm_issue_loads(
    const __half* __restrict__ X, const __half* __restrict__ W,
    int m0, int n0, int tid, uint32_t stage_addr, int k0)
{
#pragma unroll
    for (int t = 0; t < 2; ++t) {
        int idx = tid + t * 256;       // 0..511
        int row = idx >> 2;
        int c = idx & 3;
        const __half* src = X + (size_t)(m0 + row) * 1024 + k0 + c * 8;
        uint32_t dst = stage_addr + row * (GPADH * 2) + c * 16;
        asm volatile("cp.async.cg.shared.global [%0], [%1], 16;"
                     :: "r"(dst), "l"(src));
    }
#pragma unroll
    for (int t = 0; t < 2; ++t) {
        int idx = tid + t * 256;
        int row = idx >> 2;
        int c = idx & 3;
        const __half* src = W + (size_t)(n0 + row) * 1024 + k0 + c * 8;
        uint32_t dst = stage_addr + 128 * (GPADH * 2) + row * (GPADH * 2) + c * 16;
        asm volatile("cp.async.cg.shared.global [%0], [%1], 16;"
                     :: "r"(dst), "l"(src));
    }
}

// Mainloop producing acc[2][8][4]; shared by both GEMM kernels.
__device__ __forceinline__ void gemm_mainloop(
    const __half* __restrict__ X, const __half* __restrict__ W,
    const __half* smem, uint32_t sb, int m0, int n0, int tid,
    int wm, int wn, int lr, int lc, float acc[2][8][4])
{
    gemm_issue_loads(X, W, m0, n0, tid, sb + 0 * GSTAGE_BYTES, 0);
    asm volatile("cp.async.commit_group;" ::: "memory");
    gemm_issue_loads(X, W, m0, n0, tid, sb + 1 * GSTAGE_BYTES, GBK);
    asm volatile("cp.async.commit_group;" ::: "memory");
    gemm_issue_loads(X, W, m0, n0, tid, sb + 2 * GSTAGE_BYTES, 2 * GBK);
    asm volatile("cp.async.commit_group;" ::: "memory");

    const int NK = 1024 / GBK;   // 32
    for (int s = 0; s < NK; ++s) {
        int t = s + 3;
        if (t < NK)
            gemm_issue_loads(X, W, m0, n0, tid,
                             sb + (t % GNSTAGE) * GSTAGE_BYTES, t * GBK);
        asm volatile("cp.async.commit_group;" ::: "memory");
        asm volatile("cp.async.wait_group 3;" ::: "memory");
        __syncthreads();

        const __half* As = smem + (s % GNSTAGE) * (GSTAGE_BYTES / 2);
        const __half* Bs = As + 128 * GPADH;

#pragma unroll
        for (int kk = 0; kk < 2; ++kk) {     // 2 x k16
            int k0 = kk * 16 + 2 * lc;
            uint32_t af[2][4];
#pragma unroll
            for (int mt = 0; mt < 2; ++mt) {
                int r = wm * 32 + mt * 16 + lr;
                af[mt][0] = *(const uint32_t*)&As[r * GPADH + k0];
                af[mt][1] = *(const uint32_t*)&As[(r + 8) * GPADH + k0];
                af[mt][2] = *(const uint32_t*)&As[r * GPADH + k0 + 8];
                af[mt][3] = *(const uint32_t*)&As[(r + 8) * GPADH + k0 + 8];
            }
            uint32_t bf[8][2];
#pragma unroll
            for (int nt = 0; nt < 8; ++nt) {
                int n = wn * 64 + nt * 8 + lr;
                bf[nt][0] = *(const uint32_t*)&Bs[n * GPADH + k0];
                bf[nt][1] = *(const uint32_t*)&Bs[n * GPADH + k0 + 8];
            }
#pragma unroll
            for (int mt = 0; mt < 2; ++mt)
#pragma unroll
                for (int nt = 0; nt < 8; ++nt)
                    mma_f16(acc[mt][nt], af[mt], bf[nt]);
        }
        __syncthreads();
    }
}

// ===========================================================================
// Fused QKV projection: N=3072 over Wq|Wk|Wv.
// blockIdx.x 0..7 -> Q (+bias, rope, x0.125), 8..15 -> K (+bias, rope),
// 16..23 -> V (+bias, transposed store).
// ===========================================================================
__global__ __launch_bounds__(256, 2)
void gemm_qkv_kernel(const __half* __restrict__ X, const __half* __restrict__ W,
                     const float* __restrict__ bias,
                     const float* __restrict__ cosb, const float* __restrict__ sinb,
                     __half* __restrict__ Qo, __half* __restrict__ Ko,
                     __half* __restrict__ Vo)
{
    extern __shared__ __align__(16) __half smem[];
    const uint32_t sb = smem_u32(smem);
    const int tid = threadIdx.x;
    const int wid = tid >> 5;
    const int lane = tid & 31;
    const int wm = wid >> 1;
    const int wn = wid & 1;
    const int m0 = blockIdx.y * 128;
    const int n0 = blockIdx.x * 128;          // global n in [0,3072)
    const int lr = lane >> 2;
    const int lc = lane & 3;

    float acc[2][8][4];
#pragma unroll
    for (int mt = 0; mt < 2; ++mt)
#pragma unroll
        for (int nt = 0; nt < 8; ++nt)
#pragma unroll
            for (int i = 0; i < 4; ++i) acc[mt][nt][i] = 0.0f;

    gemm_mainloop(X, W, smem, sb, m0, n0, tid, wm, wn, lr, lc, acc);

    // ---- bias add (pre-rope) ----
#pragma unroll
    for (int nt = 0; nt < 8; ++nt) {
        int ncol = n0 + wn * 64 + nt * 8 + 2 * lc;
        float b0 = __ldg(&bias[ncol]);
        float b1 = __ldg(&bias[ncol + 1]);
#pragma unroll
        for (int mt = 0; mt < 2; ++mt) {
            acc[mt][nt][0] += b0; acc[mt][nt][1] += b1;
            acc[mt][nt][2] += b0; acc[mt][nt][3] += b1;
        }
    }

    const int target = blockIdx.x >> 3;               // 0=Q, 1=K, 2=V
    const int h = ((blockIdx.x & 7) << 1) + wn;       // head (warp-wide)

    if (target < 2) {
        // ---- rope in registers: partner columns are nt and nt+4 ----
        __half* Y = (target == 0) ? Qo : Ko;
        const float qscale = (target == 0) ? 0.125f : 1.0f;
#pragma unroll
        for (int mt = 0; mt < 2; ++mt) {
            int m = m0 + wm * 32 + mt * 16 + lr;
            int b = m >> 11;
            int sq = m & 2047;
            int bh = b * HH + h;
#pragma unroll
            for (int half = 0; half < 2; ++half) {
                int sr = sq + half * 8;
                const float* cr = cosb + (size_t)sr * HD;
                const float* srn = sinb + (size_t)sr * HD;
#pragma unroll
                for (int nt = 0; nt < 4; ++nt) {
                    int dd = nt * 8 + 2 * lc;         // < 32
                    float2 c2 = *(const float2*)&cr[dd];
                    float2 s2 = *(const float2*)&srn[dd];
                    float lo0 = acc[mt][nt][2 * half];
                    float lo1 = acc[mt][nt][2 * half + 1];
                    float hi0 = acc[mt][nt + 4][2 * half];
                    float hi1 = acc[mt][nt + 4][2 * half + 1];
                    float ylo0 = (lo0 * c2.x - hi0 * s2.x) * qscale;
                    float ylo1 = (lo1 * c2.y - hi1 * s2.y) * qscale;
                    float yhi0 = (hi0 * c2.x + lo0 * s2.x) * qscale;
                    float yhi1 = (hi1 * c2.y + lo1 * s2.y) * qscale;
                    __half* dst = &Y[((size_t)bh * SS + sr) * HD + dd];
                    *(__half2*)dst = __floats2half2_rn(ylo0, ylo1);
                    *(__half2*)(dst + 32) = __floats2half2_rn(yhi0, yhi1);
                }
            }
        }
    } else {
        // ---- V transposed store [b,h,d,s] ----
#pragma unroll
        for (int nt = 0; nt < 8; ++nt) {
            int dd = nt * 8 + 2 * lc;
#pragma unroll
            for (int mt = 0; mt < 2; ++mt) {
                int m = m0 + wm * 32 + mt * 16 + lr;
                int b = m >> 11;
                int sq = m & 2047;
                int bh = b * HH + h;
                __half* Y = Vo + ((size_t)bh * HD + dd) * SS;
                Y[sq]          = __float2half_rn(acc[mt][nt][0]);
                Y[SS + sq]     = __float2half_rn(acc[mt][nt][1]);
                Y[sq + 8]      = __float2half_rn(acc[mt][nt][2]);
                Y[SS + sq + 8] = __float2half_rn(acc[mt][nt][3]);
            }
        }
    }
}

// ===========================================================================
// O-projection GEMM (fp32 output)
// ===========================================================================
__global__ __launch_bounds__(256, 2)
void gemm_o_kernel(const __half* __restrict__ X, const __half* __restrict__ W,
                   const float* __restrict__ bias, float* __restrict__ Y)
{
    extern __shared__ __align__(16) __half smem[];
    const uint32_t sb = smem_u32(smem);
    const int tid = threadIdx.x;
    const int wid = tid >> 5;
    const int lane = tid & 31;
    const int wm = wid >> 1;
    const int wn = wid & 1;
    const int m0 = blockIdx.y * 128;
    const int n0 = blockIdx.x * 128;
    const int lr = lane >> 2;
    const int lc = lane & 3;

    float acc[2][8][4];
#pragma unroll
    for (int mt = 0; mt < 2; ++mt)
#pragma unroll
        for (int nt = 0; nt < 8; ++nt)
#pragma unroll
            for (int i = 0; i < 4; ++i) acc[mt][nt][i] = 0.0f;

    gemm_mainloop(X, W, smem, sb, m0, n0, tid, wm, wn, lr, lc, acc);

#pragma unroll
    for (int nt = 0; nt < 8; ++nt) {
        int ncol = n0 + wn * 64 + nt * 8 + 2 * lc;
        float b0 = __ldg(&bias[ncol]);
        float b1 = __ldg(&bias[ncol + 1]);
#pragma unroll
        for (int mt = 0; mt < 2; ++mt) {
            int m = m0 + wm * 32 + mt * 16 + lr;
            *(float2*)&Y[(size_t)m * DD + ncol] =
                make_float2(acc[mt][nt][0] + b0, acc[mt][nt][1] + b1);
            *(float2*)&Y[(size_t)(m + 8) * DD + ncol] =
                make_float2(acc[mt][nt][2] + b0, acc[mt][nt][3] + b1);
        }
    }
}

// ===========================================================================
// Flash attention via mma.sync fp16 (Q pre-scaled by 1/8).
// BM=128 (8 warps x 16 rows), BN=64, HD=64. V transposed [d][s].
// ===========================================================================
#define FPADH 72
#define H_KS0 0
#define H_VS0 (2 * 64 * FPADH)
#define H_QP  (4 * 64 * FPADH)
#define FLASH_SMEM ((4 * 64 * FPADH + 128 * FPADH) * 2)   // 55296 bytes

__device__ __forceinline__ void flash_load_kv(
    const __half* __restrict__ Kg, const __half* __restrict__ Vtg,
    int tid, uint32_t ks_addr, uint32_t vs_addr)
{
#pragma unroll
    for (int t = 0; t < 2; ++t) {
        int idx = tid + t * 256;
        int row = idx >> 3;
        int c = idx & 7;
        const __half* srcK = Kg + row * HD + c * 8;
        const __half* srcV = Vtg + (size_t)row * SS + c * 8;
        uint32_t dK = ks_addr + (row * FPADH + c * 8) * 2;
        uint32_t dV = vs_addr + (row * FPADH + c * 8) * 2;
        asm volatile("cp.async.cg.shared.global [%0], [%1], 16;" :: "r"(dK), "l"(srcK));
        asm volatile("cp.async.cg.shared.global [%0], [%1], 16;" :: "r"(dV), "l"(srcV));
    }
}

__global__ __launch_bounds__(256, 2)
void flash_h_kernel(const __half* __restrict__ Q, const __half* __restrict__ K,
                    const __half* __restrict__ Vt, __half* __restrict__ O)
{
    extern __shared__ __align__(16) __half sm[];
    const uint32_t sb = smem_u32(sm);

    const int tid = threadIdx.x;
    const int w = tid >> 5;
    const int lane = tid & 31;
    const int lr = lane >> 2;
    const int lc = lane & 3;

    const int qt = (SS / 128 - 1) - blockIdx.x;
    const int h  = blockIdx.y;
    const int b  = blockIdx.z;
    const int bh = b * HH + h;

    const __half* Qg = Q + ((size_t)bh * SS + qt * 128) * HD;
    const __half* Kb = K + (size_t)bh * SS * HD;
    const __half* Vb = Vt + (size_t)bh * HD * SS;

    __half* QP = sm + H_QP;
#pragma unroll
    for (int t = 0; t < 4; ++t) {
        int idx = tid + t * 256;
        int row = idx >> 3;
        int c8 = (idx & 7) * 8;
        *(uint4*)&QP[row * FPADH + c8] = *(const uint4*)(Qg + row * HD + c8);
    }
    __syncthreads();

    uint32_t qa[4][4];
    {
        int r = w * 16 + lr;
#pragma unroll
        for (int kk = 0; kk < 4; ++kk) {
            int k0 = kk * 16 + 2 * lc;
            qa[kk][0] = *(const uint32_t*)&QP[r * FPADH + k0];
            qa[kk][1] = *(const uint32_t*)&QP[(r + 8) * FPADH + k0];
            qa[kk][2] = *(const uint32_t*)&QP[r * FPADH + k0 + 8];
            qa[kk][3] = *(const uint32_t*)&QP[(r + 8) * FPADH + k0 + 8];
        }
    }

    float oacc[8][4];
#pragma unroll
    for (int nt = 0; nt < 8; ++nt)
#pragma unroll
        for (int i = 0; i < 4; ++i) oacc[nt][i] = 0.0f;
    float mA = -INFINITY, mB = -INFINITY, lA = 0.0f, lB = 0.0f;

    const int jmax = 2 * qt + 1;

    flash_load_kv(Kb, Vb, tid, sb + H_KS0 * 2, sb + H_VS0 * 2);
    asm volatile("cp.async.commit_group;" ::: "memory");

    __half* Pt = QP;

    for (int j = 0; j <= jmax; ++j) {
        __syncthreads();

        if (j + 1 <= jmax) {
            int st = (j + 1) & 1;
            flash_load_kv(Kb + (size_t)(j + 1) * 64 * HD,
                          Vb + (size_t)(j + 1) * 64, tid,
                          sb + (H_KS0 + st * 64 * FPADH) * 2,
                          sb + (H_VS0 + st * 64 * FPADH) * 2);
        }
        asm volatile("cp.async.commit_group;" ::: "memory");
        asm volatile("cp.async.wait_group 1;" ::: "memory");
        __syncthreads();

        const int st = j & 1;
        const __half* Ks = sm + H_KS0 + st * 64 * FPADH;
        const __half* Vs = sm + H_VS0 + st * 64 * FPADH;

        float sacc[8][4];
#pragma unroll
        for (int nt = 0; nt < 8; ++nt)
#pragma unroll
            for (int i = 0; i < 4; ++i) sacc[nt][i] = 0.0f;

#pragma unroll
        for (int kk = 0; kk < 4; ++kk) {
            int k0 = kk * 16 + 2 * lc;
#pragma unroll
            for (int nt = 0; nt < 8; ++nt) {
                int c = nt * 8 + lr;
                uint32_t bf[2];
                bf[0] = *(const uint32_t*)&Ks[c * FPADH + k0];
                bf[1] = *(const uint32_t*)&Ks[c * FPADH + k0 + 8];
                mma_f16(sacc[nt], qa[kk], bf);
            }
        }

        if (j >= 2 * qt) {
            int rowA = qt * 128 + w * 16 + lr;
            int rowB = rowA + 8;
#pragma unroll
            for (int nt = 0; nt < 8; ++nt) {
                int c0 = j * 64 + nt * 8 + 2 * lc;
                int c1 = c0 + 1;
                if (c0 > rowA) sacc[nt][0] = -1.0e30f;
                if (c1 > rowA) sacc[nt][1] = -1.0e30f;
                if (c0 > rowB) sacc[nt][2] = -1.0e30f;
                if (c1 > rowB) sacc[nt][3] = -1.0e30f;
            }
        }

        float mxA = -INFINITY, mxB = -INFINITY;
#pragma unroll
        for (int nt = 0; nt < 8; ++nt) {
            mxA = fmaxf(mxA, fmaxf(sacc[nt][0], sacc[nt][1]));
            mxB = fmaxf(mxB, fmaxf(sacc[nt][2], sacc[nt][3]));
        }
        mxA = fmaxf(mxA, __shfl_xor_sync(0xffffffffu, mxA, 1));
        mxA = fmaxf(mxA, __shfl_xor_sync(0xffffffffu, mxA, 2));
        mxB = fmaxf(mxB, __shfl_xor_sync(0xffffffffu, mxB, 1));
        mxB = fmaxf(mxB, __shfl_xor_sync(0xffffffffu, mxB, 2));

        float mnA = fmaxf(mA, mxA);
        float mnB = fmaxf(mB, mxB);
        float corrA = __expf(mA - mnA);
        float corrB = __expf(mB - mnB);
        mA = mnA; mB = mnB;

        float rsA = 0.0f, rsB = 0.0f;
#pragma unroll
        for (int nt = 0; nt < 8; ++nt) {
            sacc[nt][0] = __expf(sacc[nt][0] - mnA);
            sacc[nt][1] = __expf(sacc[nt][1] - mnA);
            sacc[nt][2] = __expf(sacc[nt][2] - mnB);
            sacc[nt][3] = __expf(sacc[nt][3] - mnB);
            rsA += sacc[nt][0] + sacc[nt][1];
            rsB += sacc[nt][2] + sacc[nt][3];
        }
        rsA += __shfl_xor_sync(0xffffffffu, rsA, 1);
        rsA += __shfl_xor_sync(0xffffffffu, rsA, 2);
        rsB += __shfl_xor_sync(0xffffffffu, rsB, 1);
        rsB += __shfl_xor_sync(0xffffffffu, rsB, 2);
        lA = lA * corrA + rsA;
        lB = lB * corrB + rsB;

#pragma unroll
        for (int nt = 0; nt < 8; ++nt) {
            oacc[nt][0] *= corrA;
            oacc[nt][1] *= corrA;
            oacc[nt][2] *= corrB;
            oacc[nt][3] *= corrB;
        }

        {
            int rA = w * 16 + lr;
#pragma unroll
            for (int nt = 0; nt < 8; ++nt) {
                int c = nt * 8 + 2 * lc;
                *(__half2*)&Pt[rA * FPADH + c] =
                    __floats2half2_rn(sacc[nt][0], sacc[nt][1]);
                *(__half2*)&Pt[(rA + 8) * FPADH + c] =
                    __floats2half2_rn(sacc[nt][2], sacc[nt][3]);
            }
        }
        __syncwarp();

#pragma unroll
        for (int kk = 0; kk < 4; ++kk) {
            int k0 = kk * 16 + 2 * lc;
            int r = w * 16 + lr;
            uint32_t pa[4];
            pa[0] = *(const uint32_t*)&Pt[r * FPADH + k0];
            pa[1] = *(const uint32_t*)&Pt[(r + 8) * FPADH + k0];
            pa[2] = *(const uint32_t*)&Pt[r * FPADH + k0 + 8];
            pa[3] = *(const uint32_t*)&Pt[(r + 8) * FPADH + k0 + 8];
#pragma unroll
            for (int nt = 0; nt < 8; ++nt) {
                int d = nt * 8 + lr;
                uint32_t bf[2];
                bf[0] = *(const uint32_t*)&Vs[d * FPADH + k0];
                bf[1] = *(const uint32_t*)&Vs[d * FPADH + k0 + 8];
                mma_f16(oacc[nt], pa, bf);
            }
        }
        __syncwarp();
    }

    float invA = 1.0f / lA;
    float invB = 1.0f / lB;
    int rowA = qt * 128 + w * 16 + lr;
    __half* Og = O + ((size_t)b * SS) * DD + h * HD;
#pragma unroll
    for (int nt = 0; nt < 8; ++nt) {
        int d = nt * 8 + 2 * lc;
        *(__half2*)&Og[(size_t)rowA * DD + d] =
            __floats2half2_rn(oacc[nt][0] * invA, oacc[nt][1] * invA);
        *(__half2*)&Og[(size_t)(rowA + 8) * DD + d] =
            __floats2half2_rn(oacc[nt][2] * invB, oacc[nt][3] * invB);
    }
}

// ---------------------------------------------------------------------------
// kernel_launch
// Input order: x, mask, rope_cos, rope_sin, Wq, bq, Wk, bk, Wv, bv, Wo, bo
// ---------------------------------------------------------------------------
extern "C" void kernel_launch(void* const* d_in, const int* in_sizes, int n_in,
                              void* d_out, int out_size)
{
    (void)in_sizes; (void)n_in; (void)out_size;

    const float* x    = (const float*)d_in[0];
    const float* cosb = (const float*)d_in[2];
    const float* sinb = (const float*)d_in[3];
    const float* Wq = (const float*)d_in[4];
    const float* bq = (const float*)d_in[5];
    const float* Wk = (const float*)d_in[6];
    const float* bk = (const float*)d_in[7];
    const float* Wv = (const float*)d_in[8];
    const float* bv = (const float*)d_in[9];
    const float* Wo = (const float*)d_in[10];
    const float* bo = (const float*)d_in[11];
    float* out = (float*)d_out;

    __half *Qh, *Kh, *Vt, *Ch, *Xh, *Wh;
    float* biasp;
    cudaGetSymbolAddress((void**)&Qh, g_Qh);
    cudaGetSymbolAddress((void**)&Kh, g_Kh);
    cudaGetSymbolAddress((void**)&Vt, g_Vt);
    cudaGetSymbolAddress((void**)&Ch, g_ctx);
    cudaGetSymbolAddress((void**)&Xh, g_Xh);
    cudaGetSymbolAddress((void**)&Wh, g_Wh);
    cudaGetSymbolAddress((void**)&biasp, g_bias);

    cudaFuncSetAttribute(gemm_qkv_kernel,
                         cudaFuncAttributeMaxDynamicSharedMemorySize, GEMM_SMEM);
    cudaFuncSetAttribute(gemm_o_kernel,
                         cudaFuncAttributeMaxDynamicSharedMemorySize, GEMM_SMEM);
    cudaFuncSetAttribute(flash_h_kernel,
                         cudaFuncAttributeMaxDynamicSharedMemorySize, FLASH_SMEM);

    // --- convert inputs to fp16 + pack bias ---
    cvt_kernel<<<(MROWS * DD / 4 + 255) / 256, 256>>>(x, Xh, MROWS * DD / 4);
    cvt_kernel<<<(DD * DD / 4 + 255) / 256, 256>>>(Wq, Wh + 0 * DD * DD, DD * DD / 4);
    cvt_kernel<<<(DD * DD / 4 + 255) / 256, 256>>>(Wk, Wh + 1 * DD * DD, DD * DD / 4);
    cvt_kernel<<<(DD * DD / 4 + 255) / 256, 256>>>(Wv, Wh + 2 * DD * DD, DD * DD / 4);
    cvt_kernel<<<(DD * DD / 4 + 255) / 256, 256>>>(Wo, Wh + 3 * DD * DD, DD * DD / 4);
    pack_bias_kernel<<<12, 256>>>(bq, bk, bv, biasp);

    // --- fused QKV projection (+rope) ---
    gemm_qkv_kernel<<<dim3(24, 64), 256, GEMM_SMEM>>>(
        Xh, Wh, biasp, cosb, sinb, Qh, Kh, Vt);

    // --- attention ---
    flash_h_kernel<<<dim3(SS / 128, HH, BB), 256, FLASH_SMEM>>>(Qh, Kh, Vt, Ch);

    // --- output projection ---
    gemm_o_kernel<<<dim3(8, 64), 256, GEMM_SMEM>>>(Ch, Wh + 3 * DD * DD, bo, out);
}

// round 10
// speedup vs baseline: 1.4385x; 1.4385x over previous
#include <cuda_runtime.h>
#include <cuda_fp16.h>
#include <math.h>
#include <stdint.h>

// Problem constants
#define BB 4
#define HH 16
#define SS 2048
#define DD 1024
#define HD 64
#define MROWS (BB * SS)   // 8192

// ---------------------------------------------------------------------------
// Scratch (no allocations allowed -> __device__ globals)
// ---------------------------------------------------------------------------
__device__ __half g_Qh[BB * HH * SS * HD];
__device__ __half g_Kh[BB * HH * SS * HD];
__device__ __half g_Vt[BB * HH * HD * SS];   // [b,h,d,s] transposed
__device__ __half g_ctx[BB * SS * DD];
__device__ __half g_Xh[MROWS * DD];
__device__ __half g_Wh[4 * DD * DD];

// ---------------------------------------------------------------------------
// helpers
// ---------------------------------------------------------------------------
__device__ __forceinline__ uint32_t smem_u32(const void* p) {
    uint32_t a;
    asm("{ .reg .u64 t; cvta.to.shared.u64 t, %1; cvt.u32.u64 %0, t; }"
        : "=r"(a) : "l"(p));
    return a;
}

// mma.sync m16n8k16 fp16 in, fp32 accumulate (in place on d)
__device__ __forceinline__ void mma_f16(float d[4], const uint32_t a[4],
                                        const uint32_t b[2]) {
    asm volatile(
        "mma.sync.aligned.m16n8k16.row.col.f32.f16.f16.f32 "
        "{%0,%1,%2,%3}, {%4,%5,%6,%7}, {%8,%9}, {%0,%1,%2,%3};"
        : "+f"(d[0]), "+f"(d[1]), "+f"(d[2]), "+f"(d[3])
        : "r"(a[0]), "r"(a[1]), "r"(a[2]), "r"(a[3]), "r"(b[0]), "r"(b[1]));
}

// ---------------------------------------------------------------------------
// Single conversion kernel: x (2M float4) then Wq|Wk|Wv|Wo (256K float4 each)
// ---------------------------------------------------------------------------
#define XN4 (MROWS * DD / 4)        // 2097152
#define WN4 (DD * DD / 4)           // 262144

__global__ void cvt_all_kernel(const float* __restrict__ x,
                               const float* __restrict__ Wq,
                               const float* __restrict__ Wk,
                               const float* __restrict__ Wv,
                               const float* __restrict__ Wo,
                               __half* __restrict__ Xh,
                               __half* __restrict__ Wh)
{
    int i = blockIdx.x * blockDim.x + threadIdx.x;
    const float* src;
    __half* dst;
    int off;
    if (i < XN4) {
        src = x; dst = Xh; off = i;
    } else {
        int j = i - XN4;
        int w = j >> 18;            // / WN4
        off = j & (WN4 - 1);
        src = (w == 0) ? Wq : (w == 1) ? Wk : (w == 2) ? Wv : Wo;
        dst = Wh + (size_t)w * DD * DD;
    }
    float4 v = ((const float4*)src)[off];
    ((__half2*)dst)[2 * off]     = __floats2half2_rn(v.x, v.y);
    ((__half2*)dst)[2 * off + 1] = __floats2half2_rn(v.z, v.w);
}

// ---------------------------------------------------------------------------
// RoPE on both Q and K in one launch. Q gets the extra 1/8 scale.
// idx space: [0, 2 * B*H*S*32); top half = K.
// ---------------------------------------------------------------------------
__global__ void rope2_kernel(__half* __restrict__ Qp, __half* __restrict__ Kp,
                             const float* __restrict__ cosb,
                             const float* __restrict__ sinb)
{
    int idx = blockIdx.x * blockDim.x + threadIdx.x;
    const int half_n = BB * HH * SS * 32;
    bool isK = idx >= half_n;
    if (isK) idx -= half_n;
    int i = idx & 31;
    int bhs = idx >> 5;
    int s = bhs & (SS - 1);
    __half* p = (isK ? Kp : Qp) + (size_t)bhs * HD;
    float x0 = __half2float(p[i]);
    float x1 = __half2float(p[i + 32]);
    float c  = cosb[s * HD + i];
    float sn = sinb[s * HD + i];
    float y0 = x0 * c - x1 * sn;
    float y1 = x1 * c + x0 * sn;
    if (!isK) { y0 *= 0.125f; y1 *= 0.125f; }
    p[i]      = __float2half_rn(y0);
    p[i + 32] = __float2half_rn(y1);
}

// ===========================================================================
// fp16 mma.sync GEMM: Y[m][n] = sum_k X[m][k]*W[n][k] + bias[n]
// CTA tile 128x128, BK=32 halves, 8 warps (4m x 2n), warp tile 32x64.
// 4-stage cp.async ring (82KB smem, 2 CTAs/SM).
// OUT: 0 = [B,H,S,hd] half (Q/K), 1 = [B,H,hd,S] half (V transposed),
//      2 = flat fp32 (final output)
// ===========================================================================
#define GBK 32
#define GPADH 40
#define GSTAGE_BYTES (2 * 128 * GPADH * 2)   // 20480
#define GNSTAGE 4
#define GEMM_SMEM (GNSTAGE * GSTAGE_BYTES)   // 81920

__device__ __forceinline__ void gemm_issue_loads(
    const __half* __restrict__ X, const __half* __restrict__ W,
    int m0, int n0, int tid, uint32_t stage_addr, int k0)
{
#pragma unroll
    for (int t = 0; t < 2; ++t) {
        int idx = tid + t * 256;       // 0..511
        int row = idx >> 2;
        int c = idx & 3;
        const __half* src = X + (size_t)(m0 + row) * 1024 + k0 + c * 8;
        uint32_t dst = stage_addr + row * (GPADH * 2) + c * 16;
        asm volatile("cp.async.cg.shared.global [%0], [%1], 16;"
                     :: "r"(dst), "l"(src));
    }
#pragma unroll
    for (int t = 0; t < 2; ++t) {
        int idx = tid + t * 256;
        int row = idx >> 2;
        int c = idx & 3;
        const __half* src = W + (size_t)(n0 + row) * 1024 + k0 + c * 8;
        uint32_t dst = stage_addr + 128 * (GPADH * 2) + row * (GPADH * 2) + c * 16;
        asm volatile("cp.async.cg.shared.global [%0], [%1], 16;"
                     :: "r"(dst), "l"(src));
    }
}

template <int OUT>
__global__ __launch_bounds__(256, 2)
void gemm_h_kernel(const __half* __restrict__ X, const __half* __restrict__ W,
                   const float* __restrict__ bias, void* __restrict__ Yv)
{
    extern __shared__ __align__(16) __half smem[];
    const uint32_t sb = smem_u32(smem);
    const int tid = threadIdx.x;
    const int wid = tid >> 5;
    const int lane = tid & 31;
    const int wm = wid >> 1;
    const int wn = wid & 1;
    const int m0 = blockIdx.y * 128;
    const int n0 = blockIdx.x * 128;

    const int lr = lane >> 2;       // 0..7
    const int lc = lane & 3;        // 0..3

    float acc[2][8][4];
#pragma unroll
    for (int mt = 0; mt < 2; ++mt)
#pragma unroll
        for (int nt = 0; nt < 8; ++nt)
#pragma unroll
            for (int i = 0; i < 4; ++i) acc[mt][nt][i] = 0.0f;

    gemm_issue_loads(X, W, m0, n0, tid, sb + 0 * GSTAGE_BYTES, 0);
    asm volatile("cp.async.commit_group;" ::: "memory");
    gemm_issue_loads(X, W, m0, n0, tid, sb + 1 * GSTAGE_BYTES, GBK);
    asm volatile("cp.async.commit_group;" ::: "memory");
    gemm_issue_loads(X, W, m0, n0, tid, sb + 2 * GSTAGE_BYTES, 2 * GBK);
    asm volatile("cp.async.commit_group;" ::: "memory");

    const int NK = 1024 / GBK;   // 32
    for (int s = 0; s < NK; ++s) {
        int t = s + 3;
        if (t < NK)
            gemm_issue_loads(X, W, m0, n0, tid,
                             sb + (t % GNSTAGE) * GSTAGE_BYTES, t * GBK);
        asm volatile("cp.async.commit_group;" ::: "memory");
        asm volatile("cp.async.wait_group 3;" ::: "memory");
        __syncthreads();

        const __half* As = smem + (s % GNSTAGE) * (GSTAGE_BYTES / 2);
        const __half* Bs = As + 128 * GPADH;

#pragma unroll
        for (int kk = 0; kk < 2; ++kk) {     // 2 x k16
            int k0 = kk * 16 + 2 * lc;
            uint32_t af[2][4];
#pragma unroll
            for (int mt = 0; mt < 2; ++mt) {
                int r = wm * 32 + mt * 16 + lr;
                af[mt][0] = *(const uint32_t*)&As[r * GPADH + k0];
                af[mt][1] = *(const uint32_t*)&As[(r + 8) * GPADH + k0];
                af[mt][2] = *(const uint32_t*)&As[r * GPADH + k0 + 8];
                af[mt][3] = *(const uint32_t*)&As[(r + 8) * GPADH + k0 + 8];
            }
            uint32_t bf[8][2];
#pragma unroll
            for (int nt = 0; nt < 8; ++nt) {
                int n = wn * 64 + nt * 8 + lr;
                bf[nt][0] = *(const uint32_t*)&Bs[n * GPADH + k0];
                bf[nt][1] = *(const uint32_t*)&Bs[n * GPADH + k0 + 8];
            }
#pragma unroll
            for (int mt = 0; mt < 2; ++mt)
#pragma unroll
                for (int nt = 0; nt < 8; ++nt)
                    mma_f16(acc[mt][nt], af[mt], bf[nt]);
        }
        __syncthreads();
    }

    // epilogue
#pragma unroll
    for (int nt = 0; nt < 8; ++nt) {
        int ncol = n0 + wn * 64 + nt * 8 + 2 * lc;
        float b0 = __ldg(&bias[ncol]);
        float b1 = __ldg(&bias[ncol + 1]);
#pragma unroll
        for (int mt = 0; mt < 2; ++mt) {
            int m = m0 + wm * 32 + mt * 16 + lr;
            float v00 = acc[mt][nt][0] + b0, v01 = acc[mt][nt][1] + b1;
            float v10 = acc[mt][nt][2] + b0, v11 = acc[mt][nt][3] + b1;
            int b   = m >> 11;
            int sq  = m & 2047;
            int h   = ncol >> 6;
            int dd  = ncol & 63;
            int bh  = b * HH + h;
            if (OUT == 0) {          // [B,H,S,hd] half
                __half* Y = (__half*)Yv;
                *(__half2*)&Y[((size_t)bh * SS + sq) * HD + dd] =
                    __floats2half2_rn(v00, v01);
                *(__half2*)&Y[((size_t)bh * SS + sq + 8) * HD + dd] =
                    __floats2half2_rn(v10, v11);
            } else if (OUT == 1) {   // [B,H,hd,S] half (V transposed)
                __half* Y = (__half*)Yv;
                Y[((size_t)bh * HD + dd) * SS + sq]     = __float2half_rn(v00);
                Y[((size_t)bh * HD + dd + 1) * SS + sq] = __float2half_rn(v01);
                Y[((size_t)bh * HD + dd) * SS + sq + 8]     = __float2half_rn(v10);
                Y[((size_t)bh * HD + dd + 1) * SS + sq + 8] = __float2half_rn(v11);
            } else {                 // flat fp32
                float* Y = (float*)Yv;
                *(float2*)&Y[(size_t)m * DD + ncol] = make_float2(v00, v01);
                *(float2*)&Y[(size_t)(m + 8) * DD + ncol] = make_float2(v10, v11);
            }
        }
    }
}

// ===========================================================================
// Flash attention via mma.sync fp16 (Q pre-scaled by 1/8 in rope).
// BM=128 (8 warps x 16 rows), BN=64, HD=64. V arrives transposed [d][s].
// Smem (halves, pad 72): Ks[2][64][72], Vs[2][64][72], QP[128][72].
// ===========================================================================
#define FPADH 72
#define H_KS0 0
#define H_VS0 (2 * 64 * FPADH)              // 9216
#define H_QP  (4 * 64 * FPADH)              // 18432
#define FLASH_SMEM ((4 * 64 * FPADH + 128 * FPADH) * 2)   // 55296 bytes

__device__ __forceinline__ void flash_load_kv(
    const __half* __restrict__ Kg, const __half* __restrict__ Vtg,
    int tid, uint32_t ks_addr, uint32_t vs_addr)
{
#pragma unroll
    for (int t = 0; t < 2; ++t) {
        int idx = tid + t * 256;    // 0..511
        int row = idx >> 3;
        int c = idx & 7;
        const __half* srcK = Kg + row * HD + c * 8;
        const __half* srcV = Vtg + (size_t)row * SS + c * 8;
        uint32_t dK = ks_addr + (row * FPADH + c * 8) * 2;
        uint32_t dV = vs_addr + (row * FPADH + c * 8) * 2;
        asm volatile("cp.async.cg.shared.global [%0], [%1], 16;" :: "r"(dK), "l"(srcK));
        asm volatile("cp.async.cg.shared.global [%0], [%1], 16;" :: "r"(dV), "l"(srcV));
    }
}

__global__ __launch_bounds__(256, 2)
void flash_h_kernel(const __half* __restrict__ Q, const __half* __restrict__ K,
                    const __half* __restrict__ Vt, __half* __restrict__ O)
{
    extern __shared__ __align__(16) __half sm[];
    const uint32_t sb = smem_u32(sm);

    const int tid = threadIdx.x;
    const int w = tid >> 5;
    const int lane = tid & 31;
    const int lr = lane >> 2;
    const int lc = lane & 3;

    const int qt = (SS / 128 - 1) - blockIdx.x;   // big tiles first
    const int h  = blockIdx.y;
    const int b  = blockIdx.z;
    const int bh = b * HH + h;

    const __half* Qg = Q + ((size_t)bh * SS + qt * 128) * HD;
    const __half* Kb = K + (size_t)bh * SS * HD;
    const __half* Vb = Vt + (size_t)bh * HD * SS;

    __half* QP = sm + H_QP;
#pragma unroll
    for (int t = 0; t < 4; ++t) {
        int idx = tid + t * 256;    // 0..1023
        int row = idx >> 3;
        int c8 = (idx & 7) * 8;
        *(uint4*)&QP[row * FPADH + c8] = *(const uint4*)(Qg + row * HD + c8);
    }
    __syncthreads();

    uint32_t qa[4][4];
    {
        int r = w * 16 + lr;
#pragma unroll
        for (int kk = 0; kk < 4; ++kk) {
            int k0 = kk * 16 + 2 * lc;
            qa[kk][0] = *(const uint32_t*)&QP[r * FPADH + k0];
            qa[kk][1] = *(const uint32_t*)&QP[(r + 8) * FPADH + k0];
            qa[kk][2] = *(const uint32_t*)&QP[r * FPADH + k0 + 8];
            qa[kk][3] = *(const uint32_t*)&QP[(r + 8) * FPADH + k0 + 8];
        }
    }

    float oacc[8][4];
#pragma unroll
    for (int nt = 0; nt < 8; ++nt)
#pragma unroll
        for (int i = 0; i < 4; ++i) oacc[nt][i] = 0.0f;
    float mA = -INFINITY, mB = -INFINITY, lA = 0.0f, lB = 0.0f;

    const int jmax = 2 * qt + 1;

    flash_load_kv(Kb, Vb, tid, sb + H_KS0 * 2, sb + H_VS0 * 2);
    asm volatile("cp.async.commit_group;" ::: "memory");

    __half* Pt = QP;

    for (int j = 0; j <= jmax; ++j) {
        __syncthreads();

        if (j + 1 <= jmax) {
            int st = (j + 1) & 1;
            flash_load_kv(Kb + (size_t)(j + 1) * 64 * HD,
                          Vb + (size_t)(j + 1) * 64, tid,
                          sb + (H_KS0 + st * 64 * FPADH) * 2,
                          sb + (H_VS0 + st * 64 * FPADH) * 2);
        }
        asm volatile("cp.async.commit_group;" ::: "memory");
        asm volatile("cp.async.wait_group 1;" ::: "memory");
        __syncthreads();

        const int st = j & 1;
        const __half* Ks = sm + H_KS0 + st * 64 * FPADH;
        const __half* Vs = sm + H_VS0 + st * 64 * FPADH;

        float sacc[8][4];
#pragma unroll
        for (int nt = 0; nt < 8; ++nt)
#pragma unroll
            for (int i = 0; i < 4; ++i) sacc[nt][i] = 0.0f;

#pragma unroll
        for (int kk = 0; kk < 4; ++kk) {
            int k0 = kk * 16 + 2 * lc;
#pragma unroll
            for (int nt = 0; nt < 8; ++nt) {
                int c = nt * 8 + lr;
                uint32_t bf[2];
                bf[0] = *(const uint32_t*)&Ks[c * FPADH + k0];
                bf[1] = *(const uint32_t*)&Ks[c * FPADH + k0 + 8];
                mma_f16(sacc[nt], qa[kk], bf);
            }
        }

        if (j >= 2 * qt) {
            int rowA = qt * 128 + w * 16 + lr;
            int rowB = rowA + 8;
#pragma unroll
            for (int nt = 0; nt < 8; ++nt) {
                int c0 = j * 64 + nt * 8 + 2 * lc;
                int c1 = c0 + 1;
                if (c0 > rowA) sacc[nt][0] = -1.0e30f;
                if (c1 > rowA) sacc[nt][1] = -1.0e30f;
                if (c0 > rowB) sacc[nt][2] = -1.0e30f;
                if (c1 > rowB) sacc[nt][3] = -1.0e30f;
            }
        }

        float mxA = -INFINITY, mxB = -INFINITY;
#pragma unroll
        for (int nt = 0; nt < 8; ++nt) {
            mxA = fmaxf(mxA, fmaxf(sacc[nt][0], sacc[nt][1]));
            mxB = fmaxf(mxB, fmaxf(sacc[nt][2], sacc[nt][3]));
        }
        mxA = fmaxf(mxA, __shfl_xor_sync(0xffffffffu, mxA, 1));
        mxA = fmaxf(mxA, __shfl_xor_sync(0xffffffffu, mxA, 2));
        mxB = fmaxf(mxB, __shfl_xor_sync(0xffffffffu, mxB, 1));
        mxB = fmaxf(mxB, __shfl_xor_sync(0xffffffffu, mxB, 2));

        float mnA = fmaxf(mA, mxA);
        float mnB = fmaxf(mB, mxB);
        float corrA = __expf(mA - mnA);
        float corrB = __expf(mB - mnB);
        mA = mnA; mB = mnB;

        float rsA = 0.0f, rsB = 0.0f;
#pragma unroll
        for (int nt = 0; nt < 8; ++nt) {
            sacc[nt][0] = __expf(sacc[nt][0] - mnA);
            sacc[nt][1] = __expf(sacc[nt][1] - mnA);
            sacc[nt][2] = __expf(sacc[nt][2] - mnB);
            sacc[nt][3] = __expf(sacc[nt][3] - mnB);
            rsA += sacc[nt][0] + sacc[nt][1];
            rsB += sacc[nt][2] + sacc[nt][3];
        }
        rsA += __shfl_xor_sync(0xffffffffu, rsA, 1);
        rsA += __shfl_xor_sync(0xffffffffu, rsA, 2);
        rsB += __shfl_xor_sync(0xffffffffu, rsB, 1);
        rsB += __shfl_xor_sync(0xffffffffu, rsB, 2);
        lA = lA * corrA + rsA;
        lB = lB * corrB + rsB;

#pragma unroll
        for (int nt = 0; nt < 8; ++nt) {
            oacc[nt][0] *= corrA;
            oacc[nt][1] *= corrA;
            oacc[nt][2] *= corrB;
            oacc[nt][3] *= corrB;
        }

        {
            int rA = w * 16 + lr;
#pragma unroll
            for (int nt = 0; nt < 8; ++nt) {
                int c = nt * 8 + 2 * lc;
                *(__half2*)&Pt[rA * FPADH + c] =
                    __floats2half2_rn(sacc[nt][0], sacc[nt][1]);
                *(__half2*)&Pt[(rA + 8) * FPADH + c] =
                    __floats2half2_rn(sacc[nt][2], sacc[nt][3]);
            }
        }
        __syncwarp();

#pragma unroll
        for (int kk = 0; kk < 4; ++kk) {
            int k0 = kk * 16 + 2 * lc;
            int r = w * 16 + lr;
            uint32_t pa[4];
            pa[0] = *(const uint32_t*)&Pt[r * FPADH + k0];
            pa[1] = *(const uint32_t*)&Pt[(r + 8) * FPADH + k0];
            pa[2] = *(const uint32_t*)&Pt[r * FPADH + k0 + 8];
            pa[3] = *(const uint32_t*)&Pt[(r + 8) * FPADH + k0 + 8];
#pragma unroll
            for (int nt = 0; nt < 8; ++nt) {
                int d = nt * 8 + lr;
                uint32_t bf[2];
                bf[0] = *(const uint32_t*)&Vs[d * FPADH + k0];
                bf[1] = *(const uint32_t*)&Vs[d * FPADH + k0 + 8];
                mma_f16(oacc[nt], pa, bf);
            }
        }
        __syncwarp();
    }

    float invA = 1.0f / lA;
    float invB = 1.0f / lB;
    int rowA = qt * 128 + w * 16 + lr;
    __half* Og = O + ((size_t)b * SS) * DD + h * HD;
#pragma unroll
    for (int nt = 0; nt < 8; ++nt) {
        int d = nt * 8 + 2 * lc;
        *(__half2*)&Og[(size_t)rowA * DD + d] =
            __floats2half2_rn(oacc[nt][0] * invA, oacc[nt][1] * invA);
        *(__half2*)&Og[(size_t)(rowA + 8) * DD + d] =
            __floats2half2_rn(oacc[nt][2] * invB, oacc[nt][3] * invB);
    }
}

// ---------------------------------------------------------------------------
// kernel_launch
// Input order: x, mask, rope_cos, rope_sin, Wq, bq, Wk, bk, Wv, bv, Wo, bo
// ---------------------------------------------------------------------------
extern "C" void kernel_launch(void* const* d_in, const int* in_sizes, int n_in,
                              void* d_out, int out_size)
{
    (void)in_sizes; (void)n_in; (void)out_size;

    const float* x    = (const float*)d_in[0];
    const float* cosb = (const float*)d_in[2];
    const float* sinb = (const float*)d_in[3];
    const float* Wq = (const float*)d_in[4];
    const float* bq = (const float*)d_in[5];
    const float* Wk = (const float*)d_in[6];
    const float* bk = (const float*)d_in[7];
    const float* Wv = (const float*)d_in[8];
    const float* bv = (const float*)d_in[9];
    const float* Wo = (const float*)d_in[10];
    const float* bo = (const float*)d_in[11];
    float* out = (float*)d_out;

    __half *Qh, *Kh, *Vt, *Ch, *Xh, *Wh;
    cudaGetSymbolAddress((void**)&Qh, g_Qh);
    cudaGetSymbolAddress((void**)&Kh, g_Kh);
    cudaGetSymbolAddress((void**)&Vt, g_Vt);
    cudaGetSymbolAddress((void**)&Ch, g_ctx);
    cudaGetSymbolAddress((void**)&Xh, g_Xh);
    cudaGetSymbolAddress((void**)&Wh, g_Wh);

    cudaFuncSetAttribute(gemm_h_kernel<0>,
                         cudaFuncAttributeMaxDynamicSharedMemorySize, GEMM_SMEM);
    cudaFuncSetAttribute(gemm_h_kernel<1>,
                         cudaFuncAttributeMaxDynamicSharedMemorySize, GEMM_SMEM);
    cudaFuncSetAttribute(gemm_h_kernel<2>,
                         cudaFuncAttributeMaxDynamicSharedMemorySize, GEMM_SMEM);
    cudaFuncSetAttribute(flash_h_kernel,
                         cudaFuncAttributeMaxDynamicSharedMemorySize, FLASH_SMEM);

    // --- convert all fp32 inputs to fp16 in one launch ---
    int total4 = XN4 + 4 * WN4;   // 3145728
    cvt_all_kernel<<<total4 / 256, 256>>>(x, Wq, Wk, Wv, Wo, Xh, Wh);

    dim3 ggrid(DD / 128, MROWS / 128);   // (8, 64) = 512 CTAs

    gemm_h_kernel<0><<<ggrid, 256, GEMM_SMEM>>>(Xh, Wh + 0 * DD * DD, bq, Qh);
    gemm_h_kernel<0><<<ggrid, 256, GEMM_SMEM>>>(Xh, Wh + 1 * DD * DD, bk, Kh);
    gemm_h_kernel<1><<<ggrid, 256, GEMM_SMEM>>>(Xh, Wh + 2 * DD * DD, bv, Vt);

    // --- rope on Q and K in one launch (Q gets 1/8 scale) ---
    int rope_threads = 2 * BB * HH * SS * 32;
    rope2_kernel<<<rope_threads / 256, 256>>>(Qh, Kh, cosb, sinb);

    flash_h_kernel<<<dim3(SS / 128, HH, BB), 256, FLASH_SMEM>>>(Qh, Kh, Vt, Ch);

    gemm_h_kernel<2><<<ggrid, 256, GEMM_SMEM>>>(Ch, Wh + 3 * DD * DD, bo, out);
}

// round 11
// speedup vs baseline: 1.5140x; 1.0524x over previous
#include <cuda_runtime.h>
#include <cuda_fp16.h>
#include <math.h>
#include <stdint.h>

// Problem constants
#define BB 4
#define HH 16
#define SS 2048
#define DD 1024
#define HD 64
#define MROWS (BB * SS)   // 8192

// ---------------------------------------------------------------------------
// Scratch (no allocations allowed -> __device__ globals)
// ---------------------------------------------------------------------------
__device__ __half g_Qh[BB * HH * SS * HD];
__device__ __half g_Kh[BB * HH * SS * HD];
__device__ __half g_Vt[BB * HH * HD * SS];   // [b,h,d,s] transposed
__device__ __half g_ctx[BB * SS * DD];
__device__ __half g_Xh[MROWS * DD];
__device__ __half g_Wh[4 * DD * DD];         // Wq|Wk|Wv|Wo packed
__device__ float  g_bias[3 * DD];            // bq|bk|bv packed

// ---------------------------------------------------------------------------
// helpers
// ---------------------------------------------------------------------------
__device__ __forceinline__ uint32_t smem_u32(const void* p) {
    uint32_t a;
    asm("{ .reg .u64 t; cvta.to.shared.u64 t, %1; cvt.u32.u64 %0, t; }"
        : "=r"(a) : "l"(p));
    return a;
}

// mma.sync m16n8k16 fp16 in, fp32 accumulate (in place on d)
__device__ __forceinline__ void mma_f16(float d[4], const uint32_t a[4],
                                        const uint32_t b[2]) {
    asm volatile(
        "mma.sync.aligned.m16n8k16.row.col.f32.f16.f16.f32 "
        "{%0,%1,%2,%3}, {%4,%5,%6,%7}, {%8,%9}, {%0,%1,%2,%3};"
        : "+f"(d[0]), "+f"(d[1]), "+f"(d[2]), "+f"(d[3])
        : "r"(a[0]), "r"(a[1]), "r"(a[2]), "r"(a[3]), "r"(b[0]), "r"(b[1]));
}

// ---------------------------------------------------------------------------
// Single conversion kernel + bias packing
// ---------------------------------------------------------------------------
#define XN4 (MROWS * DD / 4)        // 2097152
#define WN4 (DD * DD / 4)           // 262144

__global__ void cvt_all_kernel(const float* __restrict__ x,
                               const float* __restrict__ Wq,
                               const float* __restrict__ Wk,
                               const float* __restrict__ Wv,
                               const float* __restrict__ Wo,
                               __half* __restrict__ Xh,
                               __half* __restrict__ Wh)
{
    int i = blockIdx.x * blockDim.x + threadIdx.x;
    const float* src;
    __half* dst;
    int off;
    if (i < XN4) {
        src = x; dst = Xh; off = i;
    } else {
        int j = i - XN4;
        int w = j >> 18;            // / WN4
        off = j & (WN4 - 1);
        src = (w == 0) ? Wq : (w == 1) ? Wk : (w == 2) ? Wv : Wo;
        dst = Wh + (size_t)w * DD * DD;
    }
    float4 v = ((const float4*)src)[off];
    ((__half2*)dst)[2 * off]     = __floats2half2_rn(v.x, v.y);
    ((__half2*)dst)[2 * off + 1] = __floats2half2_rn(v.z, v.w);
}

__global__ void pack_bias_kernel(const float* __restrict__ bq,
                                 const float* __restrict__ bk,
                                 const float* __restrict__ bv,
                                 float* __restrict__ out)
{
    int i = blockIdx.x * blockDim.x + threadIdx.x;   // < 3072
    float v;
    if (i < 1024) v = bq[i];
    else if (i < 2048) v = bk[i - 1024];
    else v = bv[i - 2048];
    out[i] = v;
}

// ---------------------------------------------------------------------------
// RoPE on both Q and K in one launch. Q gets the extra 1/8 scale.
// ---------------------------------------------------------------------------
__global__ void rope2_kernel(__half* __restrict__ Qp, __half* __restrict__ Kp,
                             const float* __restrict__ cosb,
                             const float* __restrict__ sinb)
{
    int idx = blockIdx.x * blockDim.x + threadIdx.x;
    const int half_n = BB * HH * SS * 32;
    bool isK = idx >= half_n;
    if (isK) idx -= half_n;
    int i = idx & 31;
    int bhs = idx >> 5;
    int s = bhs & (SS - 1);
    __half* p = (isK ? Kp : Qp) + (size_t)bhs * HD;
    float x0 = __half2float(p[i]);
    float x1 = __half2float(p[i + 32]);
    float c  = cosb[s * HD + i];
    float sn = sinb[s * HD + i];
    float y0 = x0 * c - x1 * sn;
    float y1 = x1 * c + x0 * sn;
    if (!isK) { y0 *= 0.125f; y1 *= 0.125f; }
    p[i]      = __float2half_rn(y0);
    p[i + 32] = __float2half_rn(y1);
}

// ===========================================================================
// Shared GEMM machinery: CTA tile 128x128, BK=32 halves, 8 warps (4m x 2n),
// warp tile 32x64. 4-stage cp.async ring (82KB smem, 2 CTAs/SM).
// ===========================================================================
#define GBK 32
#define GPADH 40
#define GSTAGE_BYTES (2 * 128 * GPADH * 2)   // 20480
#define GNSTAGE 4
#define GEMM_SMEM (GNSTAGE * GSTAGE_BYTES)   // 81920

__device__ __forceinline__ void gemm_issue_loads(
    const __half* __restrict__ X, const __half* __restrict__ W,
    int m0, int n0, int tid, uint32_t stage_addr, int k0)
{
#pragma unroll
    for (int t = 0; t < 2; ++t) {
        int idx = tid + t * 256;       // 0..511
        int row = idx >> 2;
        int c = idx & 3;
        const __half* src = X + (size_t)(m0 + row) * 1024 + k0 + c * 8;
        uint32_t dst = stage_addr + row * (GPADH * 2) + c * 16;
        asm volatile("cp.async.cg.shared.global [%0], [%1], 16;"
                     :: "r"(dst), "l"(src));
    }
#pragma unroll
    for (int t = 0; t < 2; ++t) {
        int idx = tid + t * 256;
        int row = idx >> 2;
        int c = idx & 3;
        const __half* src = W + (size_t)(n0 + row) * 1024 + k0 + c * 8;
        uint32_t dst = stage_addr + 128 * (GPADH * 2) + row * (GPADH * 2) + c * 16;
        asm volatile("cp.async.cg.shared.global [%0], [%1], 16;"
                     :: "r"(dst), "l"(src));
    }
}

__device__ __forceinline__ void gemm_mainloop(
    const __half* __restrict__ X, const __half* __restrict__ W,
    const __half* smem, uint32_t sb, int m0, int n0, int tid,
    int wm, int wn, int lr, int lc, float acc[2][8][4])
{
    gemm_issue_loads(X, W, m0, n0, tid, sb + 0 * GSTAGE_BYTES, 0);
    asm volatile("cp.async.commit_group;" ::: "memory");
    gemm_issue_loads(X, W, m0, n0, tid, sb + 1 * GSTAGE_BYTES, GBK);
    asm volatile("cp.async.commit_group;" ::: "memory");
    gemm_issue_loads(X, W, m0, n0, tid, sb + 2 * GSTAGE_BYTES, 2 * GBK);
    asm volatile("cp.async.commit_group;" ::: "memory");

    const int NK = 1024 / GBK;   // 32
    for (int s = 0; s < NK; ++s) {
        int t = s + 3;
        if (t < NK)
            gemm_issue_loads(X, W, m0, n0, tid,
                             sb + (t % GNSTAGE) * GSTAGE_BYTES, t * GBK);
        asm volatile("cp.async.commit_group;" ::: "memory");
        asm volatile("cp.async.wait_group 3;" ::: "memory");
        __syncthreads();

        const __half* As = smem + (s % GNSTAGE) * (GSTAGE_BYTES / 2);
        const __half* Bs = As + 128 * GPADH;

#pragma unroll
        for (int kk = 0; kk < 2; ++kk) {     // 2 x k16
            int k0 = kk * 16 + 2 * lc;
            uint32_t af[2][4];
#pragma unroll
            for (int mt = 0; mt < 2; ++mt) {
                int r = wm * 32 + mt * 16 + lr;
                af[mt][0] = *(const uint32_t*)&As[r * GPADH + k0];
                af[mt][1] = *(const uint32_t*)&As[(r + 8) * GPADH + k0];
                af[mt][2] = *(const uint32_t*)&As[r * GPADH + k0 + 8];
                af[mt][3] = *(const uint32_t*)&As[(r + 8) * GPADH + k0 + 8];
            }
            uint32_t bf[8][2];
#pragma unroll
            for (int nt = 0; nt < 8; ++nt) {
                int n = wn * 64 + nt * 8 + lr;
                bf[nt][0] = *(const uint32_t*)&Bs[n * GPADH + k0];
                bf[nt][1] = *(const uint32_t*)&Bs[n * GPADH + k0 + 8];
            }
#pragma unroll
            for (int mt = 0; mt < 2; ++mt)
#pragma unroll
                for (int nt = 0; nt < 8; ++nt)
                    mma_f16(acc[mt][nt], af[mt], bf[nt]);
        }
        __syncthreads();
    }
}

// ===========================================================================
// Fused QKV GEMM: N=3072 over packed Wq|Wk|Wv.
// blockIdx.x 0..7 -> Q, 8..15 -> K  (half2 stores [B,H,S,hd])
// blockIdx.x 16..23 -> V (smem transpose -> coalesced [B,H,hd,S] stores)
// ===========================================================================
__global__ __launch_bounds__(256, 2)
void gemm_qkv_kernel(const __half* __restrict__ X, const __half* __restrict__ W,
                     const float* __restrict__ bias,
                     __half* __restrict__ Qo, __half* __restrict__ Ko,
                     __half* __restrict__ Vo)
{
    extern __shared__ __align__(16) __half smem[];
    const uint32_t sb = smem_u32(smem);
    const int tid = threadIdx.x;
    const int wid = tid >> 5;
    const int lane = tid & 31;
    const int wm = wid >> 1;
    const int wn = wid & 1;
    const int m0 = blockIdx.y * 128;
    const int n0 = blockIdx.x * 128;        // [0, 3072)
    const int lr = lane >> 2;
    const int lc = lane & 3;

    float acc[2][8][4];
#pragma unroll
    for (int mt = 0; mt < 2; ++mt)
#pragma unroll
        for (int nt = 0; nt < 8; ++nt)
#pragma unroll
            for (int i = 0; i < 4; ++i) acc[mt][nt][i] = 0.0f;

    gemm_mainloop(X, W, smem, sb, m0, n0, tid, wm, wn, lr, lc, acc);

    const int target = blockIdx.x >> 3;         // 0=Q, 1=K, 2=V
    const int h = ((blockIdx.x & 7) << 1) + wn; // head for this warp
    const int b = m0 >> 11;
    const int sq0 = m0 & 2047;

    if (target < 2) {
        __half* Y = (target == 0) ? Qo : Ko;
#pragma unroll
        for (int nt = 0; nt < 8; ++nt) {
            int dd = nt * 8 + 2 * lc;           // 0..63
            int ncol = n0 + wn * 64 + dd;
            float b0 = __ldg(&bias[ncol]);
            float b1 = __ldg(&bias[ncol + 1]);
#pragma unroll
            for (int mt = 0; mt < 2; ++mt) {
                int sq = sq0 + wm * 32 + mt * 16 + lr;
                int bh = b * HH + h;
                *(__half2*)&Y[((size_t)bh * SS + sq) * HD + dd] =
                    __floats2half2_rn(acc[mt][nt][0] + b0, acc[mt][nt][1] + b1);
                *(__half2*)&Y[((size_t)bh * SS + sq + 8) * HD + dd] =
                    __floats2half2_rn(acc[mt][nt][2] + b0, acc[mt][nt][3] + b1);
            }
        }
    } else {
        // V: stage transposed tile T[col][row] in smem, then coalesced store.
        __half* T = smem;                       // [128][136] halves = 34.8KB
#pragma unroll
        for (int nt = 0; nt < 8; ++nt) {
            int col = wn * 64 + nt * 8 + 2 * lc;   // 0..127
            int ncol = n0 + col;
            float b0 = __ldg(&bias[ncol]);
            float b1 = __ldg(&bias[ncol + 1]);
#pragma unroll
            for (int mt = 0; mt < 2; ++mt) {
                int row = wm * 32 + mt * 16 + lr;
                T[col * 136 + row] = __float2half_rn(acc[mt][nt][0] + b0);
                T[(col + 1) * 136 + row] = __float2half_rn(acc[mt][nt][1] + b1);
                T[col * 136 + row + 8] = __float2half_rn(acc[mt][nt][2] + b0);
                T[(col + 1) * 136 + row + 8] = __float2half_rn(acc[mt][nt][3] + b1);
            }
        }
        __syncthreads();

        // 128 d-rows x 128 s, uint4 (8 halves) per store: 2048 / 256 = 8 per thr
#pragma unroll
        for (int t = 0; t < 8; ++t) {
            int idx = tid + t * 256;
            int drow = idx >> 4;                // 0..127
            int c8 = (idx & 15) * 8;
            int hh = ((blockIdx.x & 7) << 1) + (drow >> 6);
            int dd = drow & 63;
            uint4 v = *(const uint4*)&T[drow * 136 + c8];
            *(uint4*)&Vo[((size_t)(b * HH + hh) * HD + dd) * SS + sq0 + c8] = v;
        }
    }
}

// ===========================================================================
// O-projection GEMM (fp32 output)
// ===========================================================================
__global__ __launch_bounds__(256, 2)
void gemm_o_kernel(const __half* __restrict__ X, const __half* __restrict__ W,
                   const float* __restrict__ bias, float* __restrict__ Y)
{
    extern __shared__ __align__(16) __half smem[];
    const uint32_t sb = smem_u32(smem);
    const int tid = threadIdx.x;
    const int wid = tid >> 5;
    const int lane = tid & 31;
    const int wm = wid >> 1;
    const int wn = wid & 1;
    const int m0 = blockIdx.y * 128;
    const int n0 = blockIdx.x * 128;
    const int lr = lane >> 2;
    const int lc = lane & 3;

    float acc[2][8][4];
#pragma unroll
    for (int mt = 0; mt < 2; ++mt)
#pragma unroll
        for (int nt = 0; nt < 8; ++nt)
#pragma unroll
            for (int i = 0; i < 4; ++i) acc[mt][nt][i] = 0.0f;

    gemm_mainloop(X, W, smem, sb, m0, n0, tid, wm, wn, lr, lc, acc);

#pragma unroll
    for (int nt = 0; nt < 8; ++nt) {
        int ncol = n0 + wn * 64 + nt * 8 + 2 * lc;
        float b0 = __ldg(&bias[ncol]);
        float b1 = __ldg(&bias[ncol + 1]);
#pragma unroll
        for (int mt = 0; mt < 2; ++mt) {
            int m = m0 + wm * 32 + mt * 16 + lr;
            *(float2*)&Y[(size_t)m * DD + ncol] =
                make_float2(acc[mt][nt][0] + b0, acc[mt][nt][1] + b1);
            *(float2*)&Y[(size_t)(m + 8) * DD + ncol] =
                make_float2(acc[mt][nt][2] + b0, acc[mt][nt][3] + b1);
        }
    }
}

// ===========================================================================
// Flash attention via mma.sync fp16 (Q pre-scaled by 1/8 in rope).
// BM=128 (8 warps x 16 rows), BN=64, HD=64. V arrives transposed [d][s].
// ===========================================================================
#define FPADH 72
#define H_KS0 0
#define H_VS0 (2 * 64 * FPADH)
#define H_QP  (4 * 64 * FPADH)
#define FLASH_SMEM ((4 * 64 * FPADH + 128 * FPADH) * 2)   // 55296 bytes

__device__ __forceinline__ void flash_load_kv(
    const __half* __restrict__ Kg, const __half* __restrict__ Vtg,
    int tid, uint32_t ks_addr, uint32_t vs_addr)
{
#pragma unroll
    for (int t = 0; t < 2; ++t) {
        int idx = tid + t * 256;
        int row = idx >> 3;
        int c = idx & 7;
        const __half* srcK = Kg + row * HD + c * 8;
        const __half* srcV = Vtg + (size_t)row * SS + c * 8;
        uint32_t dK = ks_addr + (row * FPADH + c * 8) * 2;
        uint32_t dV = vs_addr + (row * FPADH + c * 8) * 2;
        asm volatile("cp.async.cg.shared.global [%0], [%1], 16;" :: "r"(dK), "l"(srcK));
        asm volatile("cp.async.cg.shared.global [%0], [%1], 16;" :: "r"(dV), "l"(srcV));
    }
}

__global__ __launch_bounds__(256, 2)
void flash_h_kernel(const __half* __restrict__ Q, const __half* __restrict__ K,
                    const __half* __restrict__ Vt, __half* __restrict__ O)
{
    extern __shared__ __align__(16) __half sm[];
    const uint32_t sb = smem_u32(sm);

    const int tid = threadIdx.x;
    const int w = tid >> 5;
    const int lane = tid & 31;
    const int lr = lane >> 2;
    const int lc = lane & 3;

    const int qt = (SS / 128 - 1) - blockIdx.x;
    const int h  = blockIdx.y;
    const int b  = blockIdx.z;
    const int bh = b * HH + h;

    const __half* Qg = Q + ((size_t)bh * SS + qt * 128) * HD;
    const __half* Kb = K + (size_t)bh * SS * HD;
    const __half* Vb = Vt + (size_t)bh * HD * SS;

    __half* QP = sm + H_QP;
#pragma unroll
    for (int t = 0; t < 4; ++t) {
        int idx = tid + t * 256;
        int row = idx >> 3;
        int c8 = (idx & 7) * 8;
        *(uint4*)&QP[row * FPADH + c8] = *(const uint4*)(Qg + row * HD + c8);
    }
    __syncthreads();

    uint32_t qa[4][4];
    {
        int r = w * 16 + lr;
#pragma unroll
        for (int kk = 0; kk < 4; ++kk) {
            int k0 = kk * 16 + 2 * lc;
            qa[kk][0] = *(const uint32_t*)&QP[r * FPADH + k0];
            qa[kk][1] = *(const uint32_t*)&QP[(r + 8) * FPADH + k0];
            qa[kk][2] = *(const uint32_t*)&QP[r * FPADH + k0 + 8];
            qa[kk][3] = *(const uint32_t*)&QP[(r + 8) * FPADH + k0 + 8];
        }
    }

    float oacc[8][4];
#pragma unroll
    for (int nt = 0; nt < 8; ++nt)
#pragma unroll
        for (int i = 0; i < 4; ++i) oacc[nt][i] = 0.0f;
    float mA = -INFINITY, mB = -INFINITY, lA = 0.0f, lB = 0.0f;

    const int jmax = 2 * qt + 1;

    flash_load_kv(Kb, Vb, tid, sb + H_KS0 * 2, sb + H_VS0 * 2);
    asm volatile("cp.async.commit_group;" ::: "memory");

    __half* Pt = QP;

    for (int j = 0; j <= jmax; ++j) {
        __syncthreads();

        if (j + 1 <= jmax) {
            int st = (j + 1) & 1;
            flash_load_kv(Kb + (size_t)(j + 1) * 64 * HD,
                          Vb + (size_t)(j + 1) * 64, tid,
                          sb + (H_KS0 + st * 64 * FPADH) * 2,
                          sb + (H_VS0 + st * 64 * FPADH) * 2);
        }
        asm volatile("cp.async.commit_group;" ::: "memory");
        asm volatile("cp.async.wait_group 1;" ::: "memory");
        __syncthreads();

        const int st = j & 1;
        const __half* Ks = sm + H_KS0 + st * 64 * FPADH;
        const __half* Vs = sm + H_VS0 + st * 64 * FPADH;

        float sacc[8][4];
#pragma unroll
        for (int nt = 0; nt < 8; ++nt)
#pragma unroll
            for (int i = 0; i < 4; ++i) sacc[nt][i] = 0.0f;

#pragma unroll
        for (int kk = 0; kk < 4; ++kk) {
            int k0 = kk * 16 + 2 * lc;
#pragma unroll
            for (int nt = 0; nt < 8; ++nt) {
                int c = nt * 8 + lr;
                uint32_t bf[2];
                bf[0] = *(const uint32_t*)&Ks[c * FPADH + k0];
                bf[1] = *(const uint32_t*)&Ks[c * FPADH + k0 + 8];
                mma_f16(sacc[nt], qa[kk], bf);
            }
        }

        if (j >= 2 * qt) {
            int rowA = qt * 128 + w * 16 + lr;
            int rowB = rowA + 8;
#pragma unroll
            for (int nt = 0; nt < 8; ++nt) {
                int c0 = j * 64 + nt * 8 + 2 * lc;
                int c1 = c0 + 1;
                if (c0 > rowA) sacc[nt][0] = -1.0e30f;
                if (c1 > rowA) sacc[nt][1] = -1.0e30f;
                if (c0 > rowB) sacc[nt][2] = -1.0e30f;
                if (c1 > rowB) sacc[nt][3] = -1.0e30f;
            }
        }

        float mxA = -INFINITY, mxB = -INFINITY;
#pragma unroll
        for (int nt = 0; nt < 8; ++nt) {
            mxA = fmaxf(mxA, fmaxf(sacc[nt][0], sacc[nt][1]));
            mxB = fmaxf(mxB, fmaxf(sacc[nt][2], sacc[nt][3]));
        }
        mxA = fmaxf(mxA, __shfl_xor_sync(0xffffffffu, mxA, 1));
        mxA = fmaxf(mxA, __shfl_xor_sync(0xffffffffu, mxA, 2));
        mxB = fmaxf(mxB, __shfl_xor_sync(0xffffffffu, mxB, 1));
        mxB = fmaxf(mxB, __shfl_xor_sync(0xffffffffu, mxB, 2));

        float mnA = fmaxf(mA, mxA);
        float mnB = fmaxf(mB, mxB);
        float corrA = __expf(mA - mnA);
        float corrB = __expf(mB - mnB);
        mA = mnA; mB = mnB;

        float rsA = 0.0f, rsB = 0.0f;
#pragma unroll
        for (int nt = 0; nt < 8; ++nt) {
            sacc[nt][0] = __expf(sacc[nt][0] - mnA);
            sacc[nt][1] = __expf(sacc[nt][1] - mnA);
            sacc[nt][2] = __expf(sacc[nt][2] - mnB);
            sacc[nt][3] = __expf(sacc[nt][3] - mnB);
            rsA += sacc[nt][0] + sacc[nt][1];
            rsB += sacc[nt][2] + sacc[nt][3];
        }
        rsA += __shfl_xor_sync(0xffffffffu, rsA, 1);
        rsA += __shfl_xor_sync(0xffffffffu, rsA, 2);
        rsB += __shfl_xor_sync(0xffffffffu, rsB, 1);
        rsB += __shfl_xor_sync(0xffffffffu, rsB, 2);
        lA = lA * corrA + rsA;
        lB = lB * corrB + rsB;

#pragma unroll
        for (int nt = 0; nt < 8; ++nt) {
            oacc[nt][0] *= corrA;
            oacc[nt][1] *= corrA;
            oacc[nt][2] *= corrB;
            oacc[nt][3] *= corrB;
        }

        {
            int rA = w * 16 + lr;
#pragma unroll
            for (int nt = 0; nt < 8; ++nt) {
                int c = nt * 8 + 2 * lc;
                *(__half2*)&Pt[rA * FPADH + c] =
                    __floats2half2_rn(sacc[nt][0], sacc[nt][1]);
                *(__half2*)&Pt[(rA + 8) * FPADH + c] =
                    __floats2half2_rn(sacc[nt][2], sacc[nt][3]);
            }
        }
        __syncwarp();

#pragma unroll
        for (int kk = 0; kk < 4; ++kk) {
            int k0 = kk * 16 + 2 * lc;
            int r = w * 16 + lr;
            uint32_t pa[4];
            pa[0] = *(const uint32_t*)&Pt[r * FPADH + k0];
            pa[1] = *(const uint32_t*)&Pt[(r + 8) * FPADH + k0];
            pa[2] = *(const uint32_t*)&Pt[r * FPADH + k0 + 8];
            pa[3] = *(const uint32_t*)&Pt[(r + 8) * FPADH + k0 + 8];
#pragma unroll
            for (int nt = 0; nt < 8; ++nt) {
                int d = nt * 8 + lr;
                uint32_t bf[2];
                bf[0] = *(const uint32_t*)&Vs[d * FPADH + k0];
                bf[1] = *(const uint32_t*)&Vs[d * FPADH + k0 + 8];
                mma_f16(oacc[nt], pa, bf);
            }
        }
        __syncwarp();
    }

    float invA = 1.0f / lA;
    float invB = 1.0f / lB;
    int rowA = qt * 128 + w * 16 + lr;
    __half* Og = O + ((size_t)b * SS) * DD + h * HD;
#pragma unroll
    for (int nt = 0; nt < 8; ++nt) {
        int d = nt * 8 + 2 * lc;
        *(__half2*)&Og[(size_t)rowA * DD + d] =
            __floats2half2_rn(oacc[nt][0] * invA, oacc[nt][1] * invA);
        *(__half2*)&Og[(size_t)(rowA + 8) * DD + d] =
            __floats2half2_rn(oacc[nt][2] * invB, oacc[nt][3] * invB);
    }
}

// ---------------------------------------------------------------------------
// kernel_launch
// Input order: x, mask, rope_cos, rope_sin, Wq, bq, Wk, bk, Wv, bv, Wo, bo
// ---------------------------------------------------------------------------
extern "C" void kernel_launch(void* const* d_in, const int* in_sizes, int n_in,
                              void* d_out, int out_size)
{
    (void)in_sizes; (void)n_in; (void)out_size;

    const float* x    = (const float*)d_in[0];
    const float* cosb = (const float*)d_in[2];
    const float* sinb = (const float*)d_in[3];
    const float* Wq = (const float*)d_in[4];
    const float* bq = (const float*)d_in[5];
    const float* Wk = (const float*)d_in[6];
    const float* bk = (const float*)d_in[7];
    const float* Wv = (const float*)d_in[8];
    const float* bv = (const float*)d_in[9];
    const float* Wo = (const float*)d_in[10];
    const float* bo = (const float*)d_in[11];
    float* out = (float*)d_out;

    __half *Qh, *Kh, *Vt, *Ch, *Xh, *Wh;
    float* biasp;
    cudaGetSymbolAddress((void**)&Qh, g_Qh);
    cudaGetSymbolAddress((void**)&Kh, g_Kh);
    cudaGetSymbolAddress((void**)&Vt, g_Vt);
    cudaGetSymbolAddress((void**)&Ch, g_ctx);
    cudaGetSymbolAddress((void**)&Xh, g_Xh);
    cudaGetSymbolAddress((void**)&Wh, g_Wh);
    cudaGetSymbolAddress((void**)&biasp, g_bias);

    cudaFuncSetAttribute(gemm_qkv_kernel,
                         cudaFuncAttributeMaxDynamicSharedMemorySize, GEMM_SMEM);
    cudaFuncSetAttribute(gemm_o_kernel,
                         cudaFuncAttributeMaxDynamicSharedMemorySize, GEMM_SMEM);
    cudaFuncSetAttribute(flash_h_kernel,
                         cudaFuncAttributeMaxDynamicSharedMemorySize, FLASH_SMEM);

    // --- convert all fp32 inputs to fp16 + pack bias ---
    int total4 = XN4 + 4 * WN4;
    cvt_all_kernel<<<total4 / 256, 256>>>(x, Wq, Wk, Wv, Wo, Xh, Wh);
    pack_bias_kernel<<<12, 256>>>(bq, bk, bv, biasp);

    // --- fused QKV projection ---
    gemm_qkv_kernel<<<dim3(24, 64), 256, GEMM_SMEM>>>(Xh, Wh, biasp, Qh, Kh, Vt);

    // --- rope on Q and K (Q gets 1/8 scale) ---
    int rope_threads = 2 * BB * HH * SS * 32;
    rope2_kernel<<<rope_threads / 256, 256>>>(Qh, Kh, cosb, sinb);

    // --- attention ---
    flash_h_kernel<<<dim3(SS / 128, HH, BB), 256, FLASH_SMEM>>>(Qh, Kh, Vt, Ch);

    // --- output projection ---
    gemm_o_kernel<<<dim3(8, 64), 256, GEMM_SMEM>>>(Ch, Wh + 3 * DD * DD, bo, out);
}

// round 12
// speedup vs baseline: 1.6527x; 1.0916x over previous
#include <cuda_runtime.h>
#include <cuda_fp16.h>
#include <math.h>
#include <stdint.h>

// Problem constants
#define BB 4
#define HH 16
#define SS 2048
#define DD 1024
#define HD 64
#define MROWS (BB * SS)   // 8192

// ---------------------------------------------------------------------------
// Scratch (no allocations allowed -> __device__ globals)
// ---------------------------------------------------------------------------
__device__ __half g_Qh[BB * HH * SS * HD];
__device__ __half g_Kh[BB * HH * SS * HD];
__device__ __half g_Vt[BB * HH * HD * SS];   // [b,h,d,s] transposed
__device__ __half g_ctx[BB * SS * DD];
__device__ __half g_Xh[MROWS * DD];
__device__ __half g_Wh[4 * DD * DD];         // Wq|Wk|Wv|Wo packed
__device__ float  g_bias[3 * DD];            // bq|bk|bv packed

// ---------------------------------------------------------------------------
// helpers
// ---------------------------------------------------------------------------
__device__ __forceinline__ uint32_t smem_u32(const void* p) {
    uint32_t a;
    asm("{ .reg .u64 t; cvta.to.shared.u64 t, %1; cvt.u32.u64 %0, t; }"
        : "=r"(a) : "l"(p));
    return a;
}

// mma.sync m16n8k16 fp16 in, fp32 accumulate (in place on d)
__device__ __forceinline__ void mma_f16(float d[4], const uint32_t a[4],
                                        const uint32_t b[2]) {
    asm volatile(
        "mma.sync.aligned.m16n8k16.row.col.f32.f16.f16.f32 "
        "{%0,%1,%2,%3}, {%4,%5,%6,%7}, {%8,%9}, {%0,%1,%2,%3};"
        : "+f"(d[0]), "+f"(d[1]), "+f"(d[2]), "+f"(d[3])
        : "r"(a[0]), "r"(a[1]), "r"(a[2]), "r"(a[3]), "r"(b[0]), "r"(b[1]));
}

#define LDSM4(R0, R1, R2, R3, addr) \
    asm volatile("ldmatrix.sync.aligned.m8n8.x4.shared.b16 {%0,%1,%2,%3}, [%4];" \
                 : "=r"(R0), "=r"(R1), "=r"(R2), "=r"(R3) : "r"(addr))

// ---------------------------------------------------------------------------
// Single conversion kernel + bias packing
// ---------------------------------------------------------------------------
#define XN4 (MROWS * DD / 4)        // 2097152
#define WN4 (DD * DD / 4)           // 262144

__global__ void cvt_all_kernel(const float* __restrict__ x,
                               const float* __restrict__ Wq,
                               const float* __restrict__ Wk,
                               const float* __restrict__ Wv,
                               const float* __restrict__ Wo,
                               __half* __restrict__ Xh,
                               __half* __restrict__ Wh)
{
    int i = blockIdx.x * blockDim.x + threadIdx.x;
    const float* src;
    __half* dst;
    int off;
    if (i < XN4) {
        src = x; dst = Xh; off = i;
    } else {
        int j = i - XN4;
        int w = j >> 18;            // / WN4
        off = j & (WN4 - 1);
        src = (w == 0) ? Wq : (w == 1) ? Wk : (w == 2) ? Wv : Wo;
        dst = Wh + (size_t)w * DD * DD;
    }
    float4 v = ((const float4*)src)[off];
    ((__half2*)dst)[2 * off]     = __floats2half2_rn(v.x, v.y);
    ((__half2*)dst)[2 * off + 1] = __floats2half2_rn(v.z, v.w);
}

__global__ void pack_bias_kernel(const float* __restrict__ bq,
                                 const float* __restrict__ bk,
                                 const float* __restrict__ bv,
                                 float* __restrict__ out)
{
    int i = blockIdx.x * blockDim.x + threadIdx.x;   // < 3072
    float v;
    if (i < 1024) v = bq[i];
    else if (i < 2048) v = bk[i - 1024];
    else v = bv[i - 2048];
    out[i] = v;
}

// ---------------------------------------------------------------------------
// RoPE on Q and K, half2-vectorized: each thread does 2 (i, i+32) pairs.
// idx space: [0, 2 * B*H*S*16); top half = K. Q gets extra 1/8 scale.
// ---------------------------------------------------------------------------
__global__ void rope2_kernel(__half* __restrict__ Qp, __half* __restrict__ Kp,
                             const float* __restrict__ cosb,
                             const float* __restrict__ sinb)
{
    int idx = blockIdx.x * blockDim.x + threadIdx.x;
    const int half_n = BB * HH * SS * 16;
    bool isK = idx >= half_n;
    if (isK) idx -= half_n;
    int i2 = (idx & 15) * 2;            // 0,2,..,30
    int bhs = idx >> 4;
    int s = bhs & (SS - 1);
    __half* p = (isK ? Kp : Qp) + (size_t)bhs * HD;
    float2 xl = __half22float2(*(__half2*)&p[i2]);
    float2 xh = __half22float2(*(__half2*)&p[i2 + 32]);
    float2 c  = *(const float2*)&cosb[s * HD + i2];
    float2 sn = *(const float2*)&sinb[s * HD + i2];
    float y0 = xl.x * c.x - xh.x * sn.x;
    float y1 = xl.y * c.y - xh.y * sn.y;
    float z0 = xh.x * c.x + xl.x * sn.x;
    float z1 = xh.y * c.y + xl.y * sn.y;
    if (!isK) { y0 *= 0.125f; y1 *= 0.125f; z0 *= 0.125f; z1 *= 0.125f; }
    *(__half2*)&p[i2]      = __floats2half2_rn(y0, y1);
    *(__half2*)&p[i2 + 32] = __floats2half2_rn(z0, z1);
}

// ===========================================================================
// Shared GEMM machinery: CTA tile 128x128, BK=32 halves, 8 warps (4m x 2n),
// warp tile 32x64. 4-stage cp.async ring. ldmatrix.x4 fragment loads.
// ===========================================================================
#define GBK 32
#define GPADH 40
#define GSTAGE_BYTES (2 * 128 * GPADH * 2)   // 20480
#define GNSTAGE 4
#define GEMM_SMEM (GNSTAGE * GSTAGE_BYTES)   // 81920

__device__ __forceinline__ void gemm_issue_loads(
    const __half* __restrict__ X, const __half* __restrict__ W,
    int m0, int n0, int tid, uint32_t stage_addr, int k0)
{
#pragma unroll
    for (int t = 0; t < 2; ++t) {
        int idx = tid + t * 256;       // 0..511
        int row = idx >> 2;
        int c = idx & 3;
        const __half* src = X + (size_t)(m0 + row) * 1024 + k0 + c * 8;
        uint32_t dst = stage_addr + row * (GPADH * 2) + c * 16;
        asm volatile("cp.async.cg.shared.global [%0], [%1], 16;"
                     :: "r"(dst), "l"(src));
    }
#pragma unroll
    for (int t = 0; t < 2; ++t) {
        int idx = tid + t * 256;
        int row = idx >> 2;
        int c = idx & 3;
        const __half* src = W + (size_t)(n0 + row) * 1024 + k0 + c * 8;
        uint32_t dst = stage_addr + 128 * (GPADH * 2) + row * (GPADH * 2) + c * 16;
        asm volatile("cp.async.cg.shared.global [%0], [%1], 16;"
                     :: "r"(dst), "l"(src));
    }
}

// Mainloop with ldmatrix fragment loads.
__device__ __forceinline__ void gemm_mainloop(
    const __half* __restrict__ X, const __half* __restrict__ W,
    uint32_t sb, int m0, int n0, int tid,
    int wm, int wn, float acc[2][8][4])
{
    const int lane = tid & 31;
    const int lt = lane >> 3;       // tile index 0..3
    const int ltr = lane & 7;       // row within tile

    // A ldmatrix lane offset (halves): row = wm*32 + (lt&1)*8 + ltr, kadd = (lt>>1)*8
    const uint32_t a_off =
        ((wm * 32 + (lt & 1) * 8 + ltr) * GPADH + (lt >> 1) * 8) * 2;
    // B ldmatrix lane offset: row = wn*64 + (lt>>1)*8 + ltr, kadd = (lt&1)*8
    const uint32_t b_off = 128 * (GPADH * 2) +
        ((wn * 64 + (lt >> 1) * 8 + ltr) * GPADH + (lt & 1) * 8) * 2;

    gemm_issue_loads(X, W, m0, n0, tid, sb + 0 * GSTAGE_BYTES, 0);
    asm volatile("cp.async.commit_group;" ::: "memory");
    gemm_issue_loads(X, W, m0, n0, tid, sb + 1 * GSTAGE_BYTES, GBK);
    asm volatile("cp.async.commit_group;" ::: "memory");
    gemm_issue_loads(X, W, m0, n0, tid, sb + 2 * GSTAGE_BYTES, 2 * GBK);
    asm volatile("cp.async.commit_group;" ::: "memory");

    const int NK = 1024 / GBK;   // 32
    for (int s = 0; s < NK; ++s) {
        int t = s + 3;
        if (t < NK)
            gemm_issue_loads(X, W, m0, n0, tid,
                             sb + (t % GNSTAGE) * GSTAGE_BYTES, t * GBK);
        asm volatile("cp.async.commit_group;" ::: "memory");
        asm volatile("cp.async.wait_group 3;" ::: "memory");
        __syncthreads();

        const uint32_t st_b = sb + (s % GNSTAGE) * GSTAGE_BYTES;

#pragma unroll
        for (int kk = 0; kk < 2; ++kk) {     // 2 x k16
            uint32_t af[2][4];
#pragma unroll
            for (int mt = 0; mt < 2; ++mt) {
                LDSM4(af[mt][0], af[mt][1], af[mt][2], af[mt][3],
                      st_b + a_off + (mt * 16 * GPADH + kk * 16) * 2);
            }
            uint32_t bf[8][2];
#pragma unroll
            for (int p = 0; p < 4; ++p) {
                LDSM4(bf[2 * p][0], bf[2 * p][1], bf[2 * p + 1][0], bf[2 * p + 1][1],
                      st_b + b_off + (p * 16 * GPADH + kk * 16) * 2);
            }
#pragma unroll
            for (int mt = 0; mt < 2; ++mt)
#pragma unroll
                for (int nt = 0; nt < 8; ++nt)
                    mma_f16(acc[mt][nt], af[mt], bf[nt]);
        }
        __syncthreads();
    }
}

// ===========================================================================
// Fused QKV GEMM: N=3072 over packed Wq|Wk|Wv.
// ===========================================================================
__global__ __launch_bounds__(256, 2)
void gemm_qkv_kernel(const __half* __restrict__ X, const __half* __restrict__ W,
                     const float* __restrict__ bias,
                     __half* __restrict__ Qo, __half* __restrict__ Ko,
                     __half* __restrict__ Vo)
{
    extern __shared__ __align__(16) __half smem[];
    const uint32_t sb = smem_u32(smem);
    const int tid = threadIdx.x;
    const int wid = tid >> 5;
    const int lane = tid & 31;
    const int wm = wid >> 1;
    const int wn = wid & 1;
    const int m0 = blockIdx.y * 128;
    const int n0 = blockIdx.x * 128;        // [0, 3072)
    const int lr = lane >> 2;
    const int lc = lane & 3;

    float acc[2][8][4];
#pragma unroll
    for (int mt = 0; mt < 2; ++mt)
#pragma unroll
        for (int nt = 0; nt < 8; ++nt)
#pragma unroll
            for (int i = 0; i < 4; ++i) acc[mt][nt][i] = 0.0f;

    gemm_mainloop(X, W, sb, m0, n0, tid, wm, wn, acc);

    const int target = blockIdx.x >> 3;         // 0=Q, 1=K, 2=V
    const int h = ((blockIdx.x & 7) << 1) + wn; // head for this warp
    const int b = m0 >> 11;
    const int sq0 = m0 & 2047;

    if (target < 2) {
        __half* Y = (target == 0) ? Qo : Ko;
#pragma unroll
        for (int nt = 0; nt < 8; ++nt) {
            int dd = nt * 8 + 2 * lc;           // 0..63
            int ncol = n0 + wn * 64 + dd;
            float b0 = __ldg(&bias[ncol]);
            float b1 = __ldg(&bias[ncol + 1]);
#pragma unroll
            for (int mt = 0; mt < 2; ++mt) {
                int sq = sq0 + wm * 32 + mt * 16 + lr;
                int bh = b * HH + h;
                *(__half2*)&Y[((size_t)bh * SS + sq) * HD + dd] =
                    __floats2half2_rn(acc[mt][nt][0] + b0, acc[mt][nt][1] + b1);
                *(__half2*)&Y[((size_t)bh * SS + sq + 8) * HD + dd] =
                    __floats2half2_rn(acc[mt][nt][2] + b0, acc[mt][nt][3] + b1);
            }
        }
    } else {
        // V: stage transposed tile T[col][row] in smem, then coalesced store.
        __half* T = smem;                       // [128][136] halves
#pragma unroll
        for (int nt = 0; nt < 8; ++nt) {
            int col = wn * 64 + nt * 8 + 2 * lc;   // 0..127
            int ncol = n0 + col;
            float b0 = __ldg(&bias[ncol]);
            float b1 = __ldg(&bias[ncol + 1]);
#pragma unroll
            for (int mt = 0; mt < 2; ++mt) {
                int row = wm * 32 + mt * 16 + lr;
                T[col * 136 + row] = __float2half_rn(acc[mt][nt][0] + b0);
                T[(col + 1) * 136 + row] = __float2half_rn(acc[mt][nt][1] + b1);
                T[col * 136 + row + 8] = __float2half_rn(acc[mt][nt][2] + b0);
                T[(col + 1) * 136 + row + 8] = __float2half_rn(acc[mt][nt][3] + b1);
            }
        }
        __syncthreads();

#pragma unroll
        for (int t = 0; t < 8; ++t) {
            int idx = tid + t * 256;
            int drow = idx >> 4;                // 0..127
            int c8 = (idx & 15) * 8;
            int hh = ((blockIdx.x & 7) << 1) + (drow >> 6);
            int dd = drow & 63;
            uint4 v = *(const uint4*)&T[drow * 136 + c8];
            *(uint4*)&Vo[((size_t)(b * HH + hh) * HD + dd) * SS + sq0 + c8] = v;
        }
    }
}

// ===========================================================================
// O-projection GEMM (fp32 output)
// ===========================================================================
__global__ __launch_bounds__(256, 2)
void gemm_o_kernel(const __half* __restrict__ X, const __half* __restrict__ W,
                   const float* __restrict__ bias, float* __restrict__ Y)
{
    extern __shared__ __align__(16) __half smem[];
    const uint32_t sb = smem_u32(smem);
    const int tid = threadIdx.x;
    const int wid = tid >> 5;
    const int lane = tid & 31;
    const int wm = wid >> 1;
    const int wn = wid & 1;
    const int m0 = blockIdx.y * 128;
    const int n0 = blockIdx.x * 128;
    const int lr = lane >> 2;
    const int lc = lane & 3;

    float acc[2][8][4];
#pragma unroll
    for (int mt = 0; mt < 2; ++mt)
#pragma unroll
        for (int nt = 0; nt < 8; ++nt)
#pragma unroll
            for (int i = 0; i < 4; ++i) acc[mt][nt][i] = 0.0f;

    gemm_mainloop(X, W, sb, m0, n0, tid, wm, wn, acc);

#pragma unroll
    for (int nt = 0; nt < 8; ++nt) {
        int ncol = n0 + wn * 64 + nt * 8 + 2 * lc;
        float b0 = __ldg(&bias[ncol]);
        float b1 = __ldg(&bias[ncol + 1]);
#pragma unroll
        for (int mt = 0; mt < 2; ++mt) {
            int m = m0 + wm * 32 + mt * 16 + lr;
            *(float2*)&Y[(size_t)m * DD + ncol] =
                make_float2(acc[mt][nt][0] + b0, acc[mt][nt][1] + b1);
            *(float2*)&Y[(size_t)(m + 8) * DD + ncol] =
                make_float2(acc[mt][nt][2] + b0, acc[mt][nt][3] + b1);
        }
    }
}

// ===========================================================================
// Flash attention via mma.sync fp16 (unchanged from Round 11).
// ===========================================================================
#define FPADH 72
#define H_KS0 0
#define H_VS0 (2 * 64 * FPADH)
#define H_QP  (4 * 64 * FPADH)
#define FLASH_SMEM ((4 * 64 * FPADH + 128 * FPADH) * 2)   // 55296 bytes

__device__ __forceinline__ void flash_load_kv(
    const __half* __restrict__ Kg, const __half* __restrict__ Vtg,
    int tid, uint32_t ks_addr, uint32_t vs_addr)
{
#pragma unroll
    for (int t = 0; t < 2; ++t) {
        int idx = tid + t * 256;
        int row = idx >> 3;
        int c = idx & 7;
        const __half* srcK = Kg + row * HD + c * 8;
        const __half* srcV = Vtg + (size_t)row * SS + c * 8;
        uint32_t dK = ks_addr + (row * FPADH + c * 8) * 2;
        uint32_t dV = vs_addr + (row * FPADH + c * 8) * 2;
        asm volatile("cp.async.cg.shared.global [%0], [%1], 16;" :: "r"(dK), "l"(srcK));
        asm volatile("cp.async.cg.shared.global [%0], [%1], 16;" :: "r"(dV), "l"(srcV));
    }
}

__global__ __launch_bounds__(256, 2)
void flash_h_kernel(const __half* __restrict__ Q, const __half* __restrict__ K,
                    const __half* __restrict__ Vt, __half* __restrict__ O)
{
    extern __shared__ __align__(16) __half sm[];
    const uint32_t sb = smem_u32(sm);

    const int tid = threadIdx.x;
    const int w = tid >> 5;
    const int lane = tid & 31;
    const int lr = lane >> 2;
    const int lc = lane & 3;

    const int qt = (SS / 128 - 1) - blockIdx.x;
    const int h  = blockIdx.y;
    const int b  = blockIdx.z;
    const int bh = b * HH + h;

    const __half* Qg = Q + ((size_t)bh * SS + qt * 128) * HD;
    const __half* Kb = K + (size_t)bh * SS * HD;
    const __half* Vb = Vt + (size_t)bh * HD * SS;

    __half* QP = sm + H_QP;
#pragma unroll
    for (int t = 0; t < 4; ++t) {
        int idx = tid + t * 256;
        int row = idx >> 3;
        int c8 = (idx & 7) * 8;
        *(uint4*)&QP[row * FPADH + c8] = *(const uint4*)(Qg + row * HD + c8);
    }
    __syncthreads();

    uint32_t qa[4][4];
    {
        int r = w * 16 + lr;
#pragma unroll
        for (int kk = 0; kk < 4; ++kk) {
            int k0 = kk * 16 + 2 * lc;
            qa[kk][0] = *(const uint32_t*)&QP[r * FPADH + k0];
            qa[kk][1] = *(const uint32_t*)&QP[(r + 8) * FPADH + k0];
            qa[kk][2] = *(const uint32_t*)&QP[r * FPADH + k0 + 8];
            qa[kk][3] = *(const uint32_t*)&QP[(r + 8) * FPADH + k0 + 8];
        }
    }

    float oacc[8][4];
#pragma unroll
    for (int nt = 0; nt < 8; ++nt)
#pragma unroll
        for (int i = 0; i < 4; ++i) oacc[nt][i] = 0.0f;
    float mA = -INFINITY, mB = -INFINITY, lA = 0.0f, lB = 0.0f;

    const int jmax = 2 * qt + 1;

    flash_load_kv(Kb, Vb, tid, sb + H_KS0 * 2, sb + H_VS0 * 2);
    asm volatile("cp.async.commit_group;" ::: "memory");

    __half* Pt = QP;

    for (int j = 0; j <= jmax; ++j) {
        __syncthreads();

        if (j + 1 <= jmax) {
            int st = (j + 1) & 1;
            flash_load_kv(Kb + (size_t)(j + 1) * 64 * HD,
                          Vb + (size_t)(j + 1) * 64, tid,
                          sb + (H_KS0 + st * 64 * FPADH) * 2,
                          sb + (H_VS0 + st * 64 * FPADH) * 2);
        }
        asm volatile("cp.async.commit_group;" ::: "memory");
        asm volatile("cp.async.wait_group 1;" ::: "memory");
        __syncthreads();

        const int st = j & 1;
        const __half* Ks = sm + H_KS0 + st * 64 * FPADH;
        const __half* Vs = sm + H_VS0 + st * 64 * FPADH;

        float sacc[8][4];
#pragma unroll
        for (int nt = 0; nt < 8; ++nt)
#pragma unroll
            for (int i = 0; i < 4; ++i) sacc[nt][i] = 0.0f;

#pragma unroll
        for (int kk = 0; kk < 4; ++kk) {
            int k0 = kk * 16 + 2 * lc;
#pragma unroll
            for (int nt = 0; nt < 8; ++nt) {
                int c = nt * 8 + lr;
                uint32_t bf[2];
                bf[0] = *(const uint32_t*)&Ks[c * FPADH + k0];
                bf[1] = *(const uint32_t*)&Ks[c * FPADH + k0 + 8];
                mma_f16(sacc[nt], qa[kk], bf);
            }
        }

        if (j >= 2 * qt) {
            int rowA = qt * 128 + w * 16 + lr;
            int rowB = rowA + 8;
#pragma unroll
            for (int nt = 0; nt < 8; ++nt) {
                int c0 = j * 64 + nt * 8 + 2 * lc;
                int c1 = c0 + 1;
                if (c0 > rowA) sacc[nt][0] = -1.0e30f;
                if (c1 > rowA) sacc[nt][1] = -1.0e30f;
                if (c0 > rowB) sacc[nt][2] = -1.0e30f;
                if (c1 > rowB) sacc[nt][3] = -1.0e30f;
            }
        }

        float mxA = -INFINITY, mxB = -INFINITY;
#pragma unroll
        for (int nt = 0; nt < 8; ++nt) {
            mxA = fmaxf(mxA, fmaxf(sacc[nt][0], sacc[nt][1]));
            mxB = fmaxf(mxB, fmaxf(sacc[nt][2], sacc[nt][3]));
        }
        mxA = fmaxf(mxA, __shfl_xor_sync(0xffffffffu, mxA, 1));
        mxA = fmaxf(mxA, __shfl_xor_sync(0xffffffffu, mxA, 2));
        mxB = fmaxf(mxB, __shfl_xor_sync(0xffffffffu, mxB, 1));
        mxB = fmaxf(mxB, __shfl_xor_sync(0xffffffffu, mxB, 2));

        float mnA = fmaxf(mA, mxA);
        float mnB = fmaxf(mB, mxB);
        float corrA = __expf(mA - mnA);
        float corrB = __expf(mB - mnB);
        mA = mnA; mB = mnB;

        float rsA = 0.0f, rsB = 0.0f;
#pragma unroll
        for (int nt = 0; nt < 8; ++nt) {
            sacc[nt][0] = __expf(sacc[nt][0] - mnA);
            sacc[nt][1] = __expf(sacc[nt][1] - mnA);
            sacc[nt][2] = __expf(sacc[nt][2] - mnB);
            sacc[nt][3] = __expf(sacc[nt][3] - mnB);
            rsA += sacc[nt][0] + sacc[nt][1];
            rsB += sacc[nt][2] + sacc[nt][3];
        }
        rsA += __shfl_xor_sync(0xffffffffu, rsA, 1);
        rsA += __shfl_xor_sync(0xffffffffu, rsA, 2);
        rsB += __shfl_xor_sync(0xffffffffu, rsB, 1);
        rsB += __shfl_xor_sync(0xffffffffu, rsB, 2);
        lA = lA * corrA + rsA;
        lB = lB * corrB + rsB;

#pragma unroll
        for (int nt = 0; nt < 8; ++nt) {
            oacc[nt][0] *= corrA;
            oacc[nt][1] *= corrA;
            oacc[nt][2] *= corrB;
            oacc[nt][3] *= corrB;
        }

        {
            int rA = w * 16 + lr;
#pragma unroll
            for (int nt = 0; nt < 8; ++nt) {
                int c = nt * 8 + 2 * lc;
                *(__half2*)&Pt[rA * FPADH + c] =
                    __floats2half2_rn(sacc[nt][0], sacc[nt][1]);
                *(__half2*)&Pt[(rA + 8) * FPADH + c] =
                    __floats2half2_rn(sacc[nt][2], sacc[nt][3]);
            }
        }
        __syncwarp();

#pragma unroll
        for (int kk = 0; kk < 4; ++kk) {
            int k0 = kk * 16 + 2 * lc;
            int r = w * 16 + lr;
            uint32_t pa[4];
            pa[0] = *(const uint32_t*)&Pt[r * FPADH + k0];
            pa[1] = *(const uint32_t*)&Pt[(r + 8) * FPADH + k0];
            pa[2] = *(const uint32_t*)&Pt[r * FPADH + k0 + 8];
            pa[3] = *(const uint32_t*)&Pt[(r + 8) * FPADH + k0 + 8];
#pragma unroll
            for (int nt = 0; nt < 8; ++nt) {
                int d = nt * 8 + lr;
                uint32_t bf[2];
                bf[0] = *(const uint32_t*)&Vs[d * FPADH + k0];
                bf[1] = *(const uint32_t*)&Vs[d * FPADH + k0 + 8];
                mma_f16(oacc[nt], pa, bf);
            }
        }
        __syncwarp();
    }

    float invA = 1.0f / lA;
    float invB = 1.0f / lB;
    int rowA = qt * 128 + w * 16 + lr;
    __half* Og = O + ((size_t)b * SS) * DD + h * HD;
#pragma unroll
    for (int nt = 0; nt < 8; ++nt) {
        int d = nt * 8 + 2 * lc;
        *(__half2*)&Og[(size_t)rowA * DD + d] =
            __floats2half2_rn(oacc[nt][0] * invA, oacc[nt][1] * invA);
        *(__half2*)&Og[(size_t)(rowA + 8) * DD + d] =
            __floats2half2_rn(oacc[nt][2] * invB, oacc[nt][3] * invB);
    }
}

// ---------------------------------------------------------------------------
// kernel_launch
// Input order: x, mask, rope_cos, rope_sin, Wq, bq, Wk, bk, Wv, bv, Wo, bo
// ---------------------------------------------------------------------------
extern "C" void kernel_launch(void* const* d_in, const int* in_sizes, int n_in,
                              void* d_out, int out_size)
{
    (void)in_sizes; (void)n_in; (void)out_size;

    const float* x    = (const float*)d_in[0];
    const float* cosb = (const float*)d_in[2];
    const float* sinb = (const float*)d_in[3];
    const float* Wq = (const float*)d_in[4];
    const float* bq = (const float*)d_in[5];
    const float* Wk = (const float*)d_in[6];
    const float* bk = (const float*)d_in[7];
    const float* Wv = (const float*)d_in[8];
    const float* bv = (const float*)d_in[9];
    const float* Wo = (const float*)d_in[10];
    const float* bo = (const float*)d_in[11];
    float* out = (float*)d_out;

    __half *Qh, *Kh, *Vt, *Ch, *Xh, *Wh;
    float* biasp;
    cudaGetSymbolAddress((void**)&Qh, g_Qh);
    cudaGetSymbolAddress((void**)&Kh, g_Kh);
    cudaGetSymbolAddress((void**)&Vt, g_Vt);
    cudaGetSymbolAddress((void**)&Ch, g_ctx);
    cudaGetSymbolAddress((void**)&Xh, g_Xh);
    cudaGetSymbolAddress((void**)&Wh, g_Wh);
    cudaGetSymbolAddress((void**)&biasp, g_bias);

    cudaFuncSetAttribute(gemm_qkv_kernel,
                         cudaFuncAttributeMaxDynamicSharedMemorySize, GEMM_SMEM);
    cudaFuncSetAttribute(gemm_o_kernel,
                         cudaFuncAttributeMaxDynamicSharedMemorySize, GEMM_SMEM);
    cudaFuncSetAttribute(flash_h_kernel,
                         cudaFuncAttributeMaxDynamicSharedMemorySize, FLASH_SMEM);

    // --- convert all fp32 inputs to fp16 + pack bias ---
    int total4 = XN4 + 4 * WN4;
    cvt_all_kernel<<<total4 / 256, 256>>>(x, Wq, Wk, Wv, Wo, Xh, Wh);
    pack_bias_kernel<<<12, 256>>>(bq, bk, bv, biasp);

    // --- fused QKV projection ---
    gemm_qkv_kernel<<<dim3(24, 64), 256, GEMM_SMEM>>>(Xh, Wh, biasp, Qh, Kh, Vt);

    // --- rope on Q and K (Q gets 1/8 scale), half2-vectorized ---
    int rope_threads = 2 * BB * HH * SS * 16;
    rope2_kernel<<<rope_threads / 256, 256>>>(Qh, Kh, cosb, sinb);

    // --- attention ---
    flash_h_kernel<<<dim3(SS / 128, HH, BB), 256, FLASH_SMEM>>>(Qh, Kh, Vt, Ch);

    // --- output projection ---
    gemm_o_kernel<<<dim3(8, 64), 256, GEMM_SMEM>>>(Ch, Wh + 3 * DD * DD, bo, out);
}

// round 13
// speedup vs baseline: 1.6881x; 1.0215x over previous
#include <cuda_runtime.h>
#include <cuda_fp16.h>
#include <math.h>
#include <stdint.h>

// Problem constants
#define BB 4
#define HH 16
#define SS 2048
#define DD 1024
#define HD 64
#define MROWS (BB * SS)   // 8192

// ---------------------------------------------------------------------------
// Scratch (no allocations allowed -> __device__ globals)
// ---------------------------------------------------------------------------
__device__ __half g_Qh[BB * HH * SS * HD];
__device__ __half g_Kh[BB * HH * SS * HD];
__device__ __half g_Vt[BB * HH * HD * SS];   // [b,h,d,s] transposed
__device__ __half g_ctx[BB * SS * DD];
__device__ __half g_Xh[MROWS * DD];
__device__ __half g_Wh[4 * DD * DD];         // Wq|Wk|Wv|Wo packed
__device__ float  g_bias[3 * DD];            // bq|bk|bv packed

// ---------------------------------------------------------------------------
// helpers
// ---------------------------------------------------------------------------
__device__ __forceinline__ uint32_t smem_u32(const void* p) {
    uint32_t a;
    asm("{ .reg .u64 t; cvta.to.shared.u64 t, %1; cvt.u32.u64 %0, t; }"
        : "=r"(a) : "l"(p));
    return a;
}

// mma.sync m16n8k16 fp16 in, fp32 accumulate (in place on d)
__device__ __forceinline__ void mma_f16(float d[4], const uint32_t a[4],
                                        const uint32_t b[2]) {
    asm volatile(
        "mma.sync.aligned.m16n8k16.row.col.f32.f16.f16.f32 "
        "{%0,%1,%2,%3}, {%4,%5,%6,%7}, {%8,%9}, {%0,%1,%2,%3};"
        : "+f"(d[0]), "+f"(d[1]), "+f"(d[2]), "+f"(d[3])
        : "r"(a[0]), "r"(a[1]), "r"(a[2]), "r"(a[3]), "r"(b[0]), "r"(b[1]));
}

#define LDSM4(R0, R1, R2, R3, addr) \
    asm volatile("ldmatrix.sync.aligned.m8n8.x4.shared.b16 {%0,%1,%2,%3}, [%4];" \
                 : "=r"(R0), "=r"(R1), "=r"(R2), "=r"(R3) : "r"(addr))

// ---------------------------------------------------------------------------
// Single conversion kernel + bias packing
// ---------------------------------------------------------------------------
#define XN4 (MROWS * DD / 4)        // 2097152
#define WN4 (DD * DD / 4)           // 262144

__global__ void cvt_all_kernel(const float* __restrict__ x,
                               const float* __restrict__ Wq,
                               const float* __restrict__ Wk,
                               const float* __restrict__ Wv,
                               const float* __restrict__ Wo,
                               __half* __restrict__ Xh,
                               __half* __restrict__ Wh)
{
    int i = blockIdx.x * blockDim.x + threadIdx.x;
    const float* src;
    __half* dst;
    int off;
    if (i < XN4) {
        src = x; dst = Xh; off = i;
    } else {
        int j = i - XN4;
        int w = j >> 18;            // / WN4
        off = j & (WN4 - 1);
        src = (w == 0) ? Wq : (w == 1) ? Wk : (w == 2) ? Wv : Wo;
        dst = Wh + (size_t)w * DD * DD;
    }
    float4 v = ((const float4*)src)[off];
    ((__half2*)dst)[2 * off]     = __floats2half2_rn(v.x, v.y);
    ((__half2*)dst)[2 * off + 1] = __floats2half2_rn(v.z, v.w);
}

__global__ void pack_bias_kernel(const float* __restrict__ bq,
                                 const float* __restrict__ bk,
                                 const float* __restrict__ bv,
                                 float* __restrict__ out)
{
    int i = blockIdx.x * blockDim.x + threadIdx.x;   // < 3072
    float v;
    if (i < 1024) v = bq[i];
    else if (i < 2048) v = bk[i - 1024];
    else v = bv[i - 2048];
    out[i] = v;
}

// ---------------------------------------------------------------------------
// RoPE on Q and K, half2-vectorized. Q gets extra 1/8 scale.
// ---------------------------------------------------------------------------
__global__ void rope2_kernel(__half* __restrict__ Qp, __half* __restrict__ Kp,
                             const float* __restrict__ cosb,
                             const float* __restrict__ sinb)
{
    int idx = blockIdx.x * blockDim.x + threadIdx.x;
    const int half_n = BB * HH * SS * 16;
    bool isK = idx >= half_n;
    if (isK) idx -= half_n;
    int i2 = (idx & 15) * 2;            // 0,2,..,30
    int bhs = idx >> 4;
    int s = bhs & (SS - 1);
    __half* p = (isK ? Kp : Qp) + (size_t)bhs * HD;
    float2 xl = __half22float2(*(__half2*)&p[i2]);
    float2 xh = __half22float2(*(__half2*)&p[i2 + 32]);
    float2 c  = *(const float2*)&cosb[s * HD + i2];
    float2 sn = *(const float2*)&sinb[s * HD + i2];
    float y0 = xl.x * c.x - xh.x * sn.x;
    float y1 = xl.y * c.y - xh.y * sn.y;
    float z0 = xh.x * c.x + xl.x * sn.x;
    float z1 = xh.y * c.y + xl.y * sn.y;
    if (!isK) { y0 *= 0.125f; y1 *= 0.125f; z0 *= 0.125f; z1 *= 0.125f; }
    *(__half2*)&p[i2]      = __floats2half2_rn(y0, y1);
    *(__half2*)&p[i2 + 32] = __floats2half2_rn(z0, z1);
}

// ===========================================================================
// Shared GEMM machinery: CTA tile 128x128, BK=32 halves, 8 warps (4m x 2n),
// warp tile 32x64. 4-stage cp.async ring. ldmatrix.x4 fragment loads.
// ===========================================================================
#define GBK 32
#define GPADH 40
#define GSTAGE_BYTES (2 * 128 * GPADH * 2)   // 20480
#define GNSTAGE 4
#define GEMM_SMEM (GNSTAGE * GSTAGE_BYTES)   // 81920

__device__ __forceinline__ void gemm_issue_loads(
    const __half* __restrict__ X, const __half* __restrict__ W,
    int m0, int n0, int tid, uint32_t stage_addr, int k0)
{
#pragma unroll
    for (int t = 0; t < 2; ++t) {
        int idx = tid + t * 256;       // 0..511
        int row = idx >> 2;
        int c = idx & 3;
        const __half* src = X + (size_t)(m0 + row) * 1024 + k0 + c * 8;
        uint32_t dst = stage_addr + row * (GPADH * 2) + c * 16;
        asm volatile("cp.async.cg.shared.global [%0], [%1], 16;"
                     :: "r"(dst), "l"(src));
    }
#pragma unroll
    for (int t = 0; t < 2; ++t) {
        int idx = tid + t * 256;
        int row = idx >> 2;
        int c = idx & 3;
        const __half* src = W + (size_t)(n0 + row) * 1024 + k0 + c * 8;
        uint32_t dst = stage_addr + 128 * (GPADH * 2) + row * (GPADH * 2) + c * 16;
        asm volatile("cp.async.cg.shared.global [%0], [%1], 16;"
                     :: "r"(dst), "l"(src));
    }
}

__device__ __forceinline__ void gemm_mainloop(
    const __half* __restrict__ X, const __half* __restrict__ W,
    uint32_t sb, int m0, int n0, int tid,
    int wm, int wn, float acc[2][8][4])
{
    const int lane = tid & 31;
    const int lt = lane >> 3;       // tile index 0..3
    const int ltr = lane & 7;       // row within tile

    const uint32_t a_off =
        ((wm * 32 + (lt & 1) * 8 + ltr) * GPADH + (lt >> 1) * 8) * 2;
    const uint32_t b_off = 128 * (GPADH * 2) +
        ((wn * 64 + (lt >> 1) * 8 + ltr) * GPADH + (lt & 1) * 8) * 2;

    gemm_issue_loads(X, W, m0, n0, tid, sb + 0 * GSTAGE_BYTES, 0);
    asm volatile("cp.async.commit_group;" ::: "memory");
    gemm_issue_loads(X, W, m0, n0, tid, sb + 1 * GSTAGE_BYTES, GBK);
    asm volatile("cp.async.commit_group;" ::: "memory");
    gemm_issue_loads(X, W, m0, n0, tid, sb + 2 * GSTAGE_BYTES, 2 * GBK);
    asm volatile("cp.async.commit_group;" ::: "memory");

    const int NK = 1024 / GBK;   // 32
    for (int s = 0; s < NK; ++s) {
        int t = s + 3;
        if (t < NK)
            gemm_issue_loads(X, W, m0, n0, tid,
                             sb + (t % GNSTAGE) * GSTAGE_BYTES, t * GBK);
        asm volatile("cp.async.commit_group;" ::: "memory");
        asm volatile("cp.async.wait_group 3;" ::: "memory");
        __syncthreads();

        const uint32_t st_b = sb + (s % GNSTAGE) * GSTAGE_BYTES;

#pragma unroll
        for (int kk = 0; kk < 2; ++kk) {     // 2 x k16
            uint32_t af[2][4];
#pragma unroll
            for (int mt = 0; mt < 2; ++mt) {
                LDSM4(af[mt][0], af[mt][1], af[mt][2], af[mt][3],
                      st_b + a_off + (mt * 16 * GPADH + kk * 16) * 2);
            }
            uint32_t bf[8][2];
#pragma unroll
            for (int p = 0; p < 4; ++p) {
                LDSM4(bf[2 * p][0], bf[2 * p][1], bf[2 * p + 1][0], bf[2 * p + 1][1],
                      st_b + b_off + (p * 16 * GPADH + kk * 16) * 2);
            }
#pragma unroll
            for (int mt = 0; mt < 2; ++mt)
#pragma unroll
                for (int nt = 0; nt < 8; ++nt)
                    mma_f16(acc[mt][nt], af[mt], bf[nt]);
        }
        __syncthreads();
    }
}

// ===========================================================================
// Fused QKV GEMM: N=3072 over packed Wq|Wk|Wv.
// ===========================================================================
__global__ __launch_bounds__(256, 2)
void gemm_qkv_kernel(const __half* __restrict__ X, const __half* __restrict__ W,
                     const float* __restrict__ bias,
                     __half* __restrict__ Qo, __half* __restrict__ Ko,
                     __half* __restrict__ Vo)
{
    extern __shared__ __align__(16) __half smem[];
    const uint32_t sb = smem_u32(smem);
    const int tid = threadIdx.x;
    const int wid = tid >> 5;
    const int lane = tid & 31;
    const int wm = wid >> 1;
    const int wn = wid & 1;
    const int m0 = blockIdx.y * 128;
    const int n0 = blockIdx.x * 128;        // [0, 3072)
    const int lr = lane >> 2;
    const int lc = lane & 3;

    float acc[2][8][4];
#pragma unroll
    for (int mt = 0; mt < 2; ++mt)
#pragma unroll
        for (int nt = 0; nt < 8; ++nt)
#pragma unroll
            for (int i = 0; i < 4; ++i) acc[mt][nt][i] = 0.0f;

    gemm_mainloop(X, W, sb, m0, n0, tid, wm, wn, acc);

    const int target = blockIdx.x >> 3;         // 0=Q, 1=K, 2=V
    const int h = ((blockIdx.x & 7) << 1) + wn; // head for this warp
    const int b = m0 >> 11;
    const int sq0 = m0 & 2047;

    if (target < 2) {
        __half* Y = (target == 0) ? Qo : Ko;
#pragma unroll
        for (int nt = 0; nt < 8; ++nt) {
            int dd = nt * 8 + 2 * lc;           // 0..63
            int ncol = n0 + wn * 64 + dd;
            float b0 = __ldg(&bias[ncol]);
            float b1 = __ldg(&bias[ncol + 1]);
#pragma unroll
            for (int mt = 0; mt < 2; ++mt) {
                int sq = sq0 + wm * 32 + mt * 16 + lr;
                int bh = b * HH + h;
                *(__half2*)&Y[((size_t)bh * SS + sq) * HD + dd] =
                    __floats2half2_rn(acc[mt][nt][0] + b0, acc[mt][nt][1] + b1);
                *(__half2*)&Y[((size_t)bh * SS + sq + 8) * HD + dd] =
                    __floats2half2_rn(acc[mt][nt][2] + b0, acc[mt][nt][3] + b1);
            }
        }
    } else {
        // V: stage transposed tile T[col][row] in smem, then coalesced store.
        __half* T = smem;                       // [128][136] halves
#pragma unroll
        for (int nt = 0; nt < 8; ++nt) {
            int col = wn * 64 + nt * 8 + 2 * lc;   // 0..127
            int ncol = n0 + col;
            float b0 = __ldg(&bias[ncol]);
            float b1 = __ldg(&bias[ncol + 1]);
#pragma unroll
            for (int mt = 0; mt < 2; ++mt) {
                int row = wm * 32 + mt * 16 + lr;
                T[col * 136 + row] = __float2half_rn(acc[mt][nt][0] + b0);
                T[(col + 1) * 136 + row] = __float2half_rn(acc[mt][nt][1] + b1);
                T[col * 136 + row + 8] = __float2half_rn(acc[mt][nt][2] + b0);
                T[(col + 1) * 136 + row + 8] = __float2half_rn(acc[mt][nt][3] + b1);
            }
        }
        __syncthreads();

#pragma unroll
        for (int t = 0; t < 8; ++t) {
            int idx = tid + t * 256;
            int drow = idx >> 4;                // 0..127
            int c8 = (idx & 15) * 8;
            int hh = ((blockIdx.x & 7) << 1) + (drow >> 6);
            int dd = drow & 63;
            uint4 v = *(const uint4*)&T[drow * 136 + c8];
            *(uint4*)&Vo[((size_t)(b * HH + hh) * HD + dd) * SS + sq0 + c8] = v;
        }
    }
}

// ===========================================================================
// O-projection GEMM (fp32 output)
// ===========================================================================
__global__ __launch_bounds__(256, 2)
void gemm_o_kernel(const __half* __restrict__ X, const __half* __restrict__ W,
                   const float* __restrict__ bias, float* __restrict__ Y)
{
    extern __shared__ __align__(16) __half smem[];
    const uint32_t sb = smem_u32(smem);
    const int tid = threadIdx.x;
    const int wid = tid >> 5;
    const int lane = tid & 31;
    const int wm = wid >> 1;
    const int wn = wid & 1;
    const int m0 = blockIdx.y * 128;
    const int n0 = blockIdx.x * 128;
    const int lr = lane >> 2;
    const int lc = lane & 3;

    float acc[2][8][4];
#pragma unroll
    for (int mt = 0; mt < 2; ++mt)
#pragma unroll
        for (int nt = 0; nt < 8; ++nt)
#pragma unroll
            for (int i = 0; i < 4; ++i) acc[mt][nt][i] = 0.0f;

    gemm_mainloop(X, W, sb, m0, n0, tid, wm, wn, acc);

#pragma unroll
    for (int nt = 0; nt < 8; ++nt) {
        int ncol = n0 + wn * 64 + nt * 8 + 2 * lc;
        float b0 = __ldg(&bias[ncol]);
        float b1 = __ldg(&bias[ncol + 1]);
#pragma unroll
        for (int mt = 0; mt < 2; ++mt) {
            int m = m0 + wm * 32 + mt * 16 + lr;
            *(float2*)&Y[(size_t)m * DD + ncol] =
                make_float2(acc[mt][nt][0] + b0, acc[mt][nt][1] + b1);
            *(float2*)&Y[(size_t)(m + 8) * DD + ncol] =
                make_float2(acc[mt][nt][2] + b0, acc[mt][nt][3] + b1);
        }
    }
}

// ===========================================================================
// Flash attention via mma.sync fp16, ldmatrix fragment loads everywhere.
// BM=128 (8 warps x 16 rows), BN=64, HD=64. V arrives transposed [d][s].
// ===========================================================================
#define FPADH 72
#define H_KS0 0
#define H_VS0 (2 * 64 * FPADH)
#define H_QP  (4 * 64 * FPADH)
#define FLASH_SMEM ((4 * 64 * FPADH + 128 * FPADH) * 2)   // 55296 bytes

__device__ __forceinline__ void flash_load_kv(
    const __half* __restrict__ Kg, const __half* __restrict__ Vtg,
    int tid, uint32_t ks_addr, uint32_t vs_addr)
{
#pragma unroll
    for (int t = 0; t < 2; ++t) {
        int idx = tid + t * 256;
        int row = idx >> 3;
        int c = idx & 7;
        const __half* srcK = Kg + row * HD + c * 8;
        const __half* srcV = Vtg + (size_t)row * SS + c * 8;
        uint32_t dK = ks_addr + (row * FPADH + c * 8) * 2;
        uint32_t dV = vs_addr + (row * FPADH + c * 8) * 2;
        asm volatile("cp.async.cg.shared.global [%0], [%1], 16;" :: "r"(dK), "l"(srcK));
        asm volatile("cp.async.cg.shared.global [%0], [%1], 16;" :: "r"(dV), "l"(srcV));
    }
}

__global__ __launch_bounds__(256, 2)
void flash_h_kernel(const __half* __restrict__ Q, const __half* __restrict__ K,
                    const __half* __restrict__ Vt, __half* __restrict__ O)
{
    extern __shared__ __align__(16) __half sm[];
    const uint32_t sb = smem_u32(sm);

    const int tid = threadIdx.x;
    const int w = tid >> 5;
    const int lane = tid & 31;
    const int lr = lane >> 2;
    const int lc = lane & 3;
    const int lt = lane >> 3;       // ldmatrix tile index 0..3
    const int ltr = lane & 7;       // row within tile

    const int qt = (SS / 128 - 1) - blockIdx.x;
    const int h  = blockIdx.y;
    const int b  = blockIdx.z;
    const int bh = b * HH + h;

    const __half* Qg = Q + ((size_t)bh * SS + qt * 128) * HD;
    const __half* Kb = K + (size_t)bh * SS * HD;
    const __half* Vb = Vt + (size_t)bh * HD * SS;

    // ldmatrix lane byte offsets (B-layout for K/V, A-layout for P)
    const uint32_t kv_off =
        (((lt >> 1) * 8 + ltr) * FPADH + (lt & 1) * 8) * 2;
    const uint32_t p_off =
        ((w * 16 + (lt & 1) * 8 + ltr) * FPADH + (lt >> 1) * 8) * 2;
    const uint32_t qp_base = sb + H_QP * 2;

    __half* QP = sm + H_QP;
#pragma unroll
    for (int t = 0; t < 4; ++t) {
        int idx = tid + t * 256;
        int row = idx >> 3;
        int c8 = (idx & 7) * 8;
        *(uint4*)&QP[row * FPADH + c8] = *(const uint4*)(Qg + row * HD + c8);
    }
    __syncthreads();

    // Q fragments via ldmatrix (A-layout, verified identical bits to scalar)
    uint32_t qa[4][4];
#pragma unroll
    for (int kk = 0; kk < 4; ++kk) {
        LDSM4(qa[kk][0], qa[kk][1], qa[kk][2], qa[kk][3],
              qp_base + p_off + kk * 32);
    }

    float oacc[8][4];
#pragma unroll
    for (int nt = 0; nt < 8; ++nt)
#pragma unroll
        for (int i = 0; i < 4; ++i) oacc[nt][i] = 0.0f;
    float mA = -INFINITY, mB = -INFINITY, lA = 0.0f, lB = 0.0f;

    const int jmax = 2 * qt + 1;

    flash_load_kv(Kb, Vb, tid, sb + H_KS0 * 2, sb + H_VS0 * 2);
    asm volatile("cp.async.commit_group;" ::: "memory");

    __half* Pt = QP;

    for (int j = 0; j <= jmax; ++j) {
        __syncthreads();

        if (j + 1 <= jmax) {
            int st = (j + 1) & 1;
            flash_load_kv(Kb + (size_t)(j + 1) * 64 * HD,
                          Vb + (size_t)(j + 1) * 64, tid,
                          sb + (H_KS0 + st * 64 * FPADH) * 2,
                          sb + (H_VS0 + st * 64 * FPADH) * 2);
        }
        asm volatile("cp.async.commit_group;" ::: "memory");
        asm volatile("cp.async.wait_group 1;" ::: "memory");
        __syncthreads();

        const int st = j & 1;
        const uint32_t ksb = sb + (H_KS0 + st * 64 * FPADH) * 2;
        const uint32_t vsb = sb + (H_VS0 + st * 64 * FPADH) * 2;

        // ---- S = (Q/8) K^T via ldmatrix ----
        float sacc[8][4];
#pragma unroll
        for (int nt = 0; nt < 8; ++nt)
#pragma unroll
            for (int i = 0; i < 4; ++i) sacc[nt][i] = 0.0f;

#pragma unroll
        for (int kk = 0; kk < 4; ++kk) {
#pragma unroll
            for (int p = 0; p < 4; ++p) {
                uint32_t bf[4];
                LDSM4(bf[0], bf[1], bf[2], bf[3],
                      ksb + kv_off + (p * 16 * FPADH + kk * 16) * 2);
                mma_f16(sacc[2 * p], qa[kk], bf);
                mma_f16(sacc[2 * p + 1], qa[kk], bf + 2);
            }
        }

        if (j >= 2 * qt) {
            int rowA = qt * 128 + w * 16 + lr;
            int rowB = rowA + 8;
#pragma unroll
            for (int nt = 0; nt < 8; ++nt) {
                int c0 = j * 64 + nt * 8 + 2 * lc;
                int c1 = c0 + 1;
                if (c0 > rowA) sacc[nt][0] = -1.0e30f;
                if (c1 > rowA) sacc[nt][1] = -1.0e30f;
                if (c0 > rowB) sacc[nt][2] = -1.0e30f;
                if (c1 > rowB) sacc[nt][3] = -1.0e30f;
            }
        }

        float mxA = -INFINITY, mxB = -INFINITY;
#pragma unroll
        for (int nt = 0; nt < 8; ++nt) {
            mxA = fmaxf(mxA, fmaxf(sacc[nt][0], sacc[nt][1]));
            mxB = fmaxf(mxB, fmaxf(sacc[nt][2], sacc[nt][3]));
        }
        mxA = fmaxf(mxA, __shfl_xor_sync(0xffffffffu, mxA, 1));
        mxA = fmaxf(mxA, __shfl_xor_sync(0xffffffffu, mxA, 2));
        mxB = fmaxf(mxB, __shfl_xor_sync(0xffffffffu, mxB, 1));
        mxB = fmaxf(mxB, __shfl_xor_sync(0xffffffffu, mxB, 2));

        float mnA = fmaxf(mA, mxA);
        float mnB = fmaxf(mB, mxB);
        float corrA = __expf(mA - mnA);
        float corrB = __expf(mB - mnB);
        mA = mnA; mB = mnB;

        float rsA = 0.0f, rsB = 0.0f;
#pragma unroll
        for (int nt = 0; nt < 8; ++nt) {
            sacc[nt][0] = __expf(sacc[nt][0] - mnA);
            sacc[nt][1] = __expf(sacc[nt][1] - mnA);
            sacc[nt][2] = __expf(sacc[nt][2] - mnB);
            sacc[nt][3] = __expf(sacc[nt][3] - mnB);
            rsA += sacc[nt][0] + sacc[nt][1];
            rsB += sacc[nt][2] + sacc[nt][3];
        }
        rsA += __shfl_xor_sync(0xffffffffu, rsA, 1);
        rsA += __shfl_xor_sync(0xffffffffu, rsA, 2);
        rsB += __shfl_xor_sync(0xffffffffu, rsB, 1);
        rsB += __shfl_xor_sync(0xffffffffu, rsB, 2);
        lA = lA * corrA + rsA;
        lB = lB * corrB + rsB;

#pragma unroll
        for (int nt = 0; nt < 8; ++nt) {
            oacc[nt][0] *= corrA;
            oacc[nt][1] *= corrA;
            oacc[nt][2] *= corrB;
            oacc[nt][3] *= corrB;
        }

        {
            int rA = w * 16 + lr;
#pragma unroll
            for (int nt = 0; nt < 8; ++nt) {
                int c = nt * 8 + 2 * lc;
                *(__half2*)&Pt[rA * FPADH + c] =
                    __floats2half2_rn(sacc[nt][0], sacc[nt][1]);
                *(__half2*)&Pt[(rA + 8) * FPADH + c] =
                    __floats2half2_rn(sacc[nt][2], sacc[nt][3]);
            }
        }
        __syncwarp();

        // ---- O += P V via ldmatrix (P: A-layout, V: B-layout) ----
#pragma unroll
        for (int kk = 0; kk < 4; ++kk) {
            uint32_t pa[4];
            LDSM4(pa[0], pa[1], pa[2], pa[3], qp_base + p_off + kk * 32);
#pragma unroll
            for (int p = 0; p < 4; ++p) {
                uint32_t vf[4];
                LDSM4(vf[0], vf[1], vf[2], vf[3],
                      vsb + kv_off + (p * 16 * FPADH + kk * 16) * 2);
                mma_f16(oacc[2 * p], pa, vf);
                mma_f16(oacc[2 * p + 1], pa, vf + 2);
            }
        }
        __syncwarp();
    }

    float invA = 1.0f / lA;
    float invB = 1.0f / lB;
    int rowA = qt * 128 + w * 16 + lr;
    __half* Og = O + ((size_t)b * SS) * DD + h * HD;
#pragma unroll
    for (int nt = 0; nt < 8; ++nt) {
        int d = nt * 8 + 2 * lc;
        *(__half2*)&Og[(size_t)rowA * DD + d] =
            __floats2half2_rn(oacc[nt][0] * invA, oacc[nt][1] * invA);
        *(__half2*)&Og[(size_t)(rowA + 8) * DD + d] =
            __floats2half2_rn(oacc[nt][2] * invB, oacc[nt][3] * invB);
    }
}

// ---------------------------------------------------------------------------
// kernel_launch
// Input order: x, mask, rope_cos, rope_sin, Wq, bq, Wk, bk, Wv, bv, Wo, bo
// ---------------------------------------------------------------------------
extern "C" void kernel_launch(void* const* d_in, const int* in_sizes, int n_in,
                              void* d_out, int out_size)
{
    (void)in_sizes; (void)n_in; (void)out_size;

    const float* x    = (const float*)d_in[0];
    const float* cosb = (const float*)d_in[2];
    const float* sinb = (const float*)d_in[3];
    const float* Wq = (const float*)d_in[4];
    const float* bq = (const float*)d_in[5];
    const float* Wk = (const float*)d_in[6];
    const float* bk = (const float*)d_in[7];
    const float* Wv = (const float*)d_in[8];
    const float* bv = (const float*)d_in[9];
    const float* Wo = (const float*)d_in[10];
    const float* bo = (const float*)d_in[11];
    float* out = (float*)d_out;

    __half *Qh, *Kh, *Vt, *Ch, *Xh, *Wh;
    float* biasp;
    cudaGetSymbolAddress((void**)&Qh, g_Qh);
    cudaGetSymbolAddress((void**)&Kh, g_Kh);
    cudaGetSymbolAddress((void**)&Vt, g_Vt);
    cudaGetSymbolAddress((void**)&Ch, g_ctx);
    cudaGetSymbolAddress((void**)&Xh, g_Xh);
    cudaGetSymbolAddress((void**)&Wh, g_Wh);
    cudaGetSymbolAddress((void**)&biasp, g_bias);

    cudaFuncSetAttribute(gemm_qkv_kernel,
                         cudaFuncAttributeMaxDynamicSharedMemorySize, GEMM_SMEM);
    cudaFuncSetAttribute(gemm_o_kernel,
                         cudaFuncAttributeMaxDynamicSharedMemorySize, GEMM_SMEM);
    cudaFuncSetAttribute(flash_h_kernel,
                         cudaFuncAttributeMaxDynamicSharedMemorySize, FLASH_SMEM);

    // --- convert all fp32 inputs to fp16 + pack bias ---
    int total4 = XN4 + 4 * WN4;
    cvt_all_kernel<<<total4 / 256, 256>>>(x, Wq, Wk, Wv, Wo, Xh, Wh);
    pack_bias_kernel<<<12, 256>>>(bq, bk, bv, biasp);

    // --- fused QKV projection ---
    gemm_qkv_kernel<<<dim3(24, 64), 256, GEMM_SMEM>>>(Xh, Wh, biasp, Qh, Kh, Vt);

    // --- rope on Q and K (Q gets 1/8 scale), half2-vectorized ---
    int rope_threads = 2 * BB * HH * SS * 16;
    rope2_kernel<<<rope_threads / 256, 256>>>(Qh, Kh, cosb, sinb);

    // --- attention ---
    flash_h_kernel<<<dim3(SS / 128, HH, BB), 256, FLASH_SMEM>>>(Qh, Kh, Vt, Ch);

    // --- output projection ---
    gemm_o_kernel<<<dim3(8, 64), 256, GEMM_SMEM>>>(Ch, Wh + 3 * DD * DD, bo, out);
}